// round 2
// baseline (speedup 1.0000x reference)
#include <cuda_runtime.h>
#include <cstdint>

#define N_NODES 50000
#define N_EDGES 800000
#define D 128
#define DE 16
#define K1DIM 272   // 2*D + DE
#define K3DIM 256   // 2*D
#define TE 64       // edges/nodes per tile

// ---------------- scratch (static device arrays; no allocation) -------------
__device__ int   g_is64;
__device__ int   g_row[N_EDGES];
__device__ int   g_col[N_EDGES];
__device__ float g_h[(size_t)N_EDGES * D];     // edge hidden (409.6 MB)
__device__ float g_agg[(size_t)N_NODES * D];   // scatter target
__device__ float g_t[(size_t)N_NODES * D];     // node hidden

__device__ __forceinline__ float silu_f(float v) {
    return v / (1.0f + __expf(-v));
}

// ---------------- index dtype detection + conversion ------------------------
// jnp.int64 without x64 enabled is silently int32; detect which one we got.
// If int64 (little-endian), the high word of every entry is 0 (ids < 2^31).
__global__ void k_detect(const int* ei32) {
    if (blockIdx.x == 0 && threadIdx.x == 0) {
        int is64 = 1;
        #pragma unroll 1
        for (int i = 0; i < 64; ++i)
            if (ei32[2 * i + 1] != 0) { is64 = 0; break; }
        g_is64 = is64;
    }
}

__global__ void k_convert(const void* ei) {
    int e = blockIdx.x * blockDim.x + threadIdx.x;
    if (e >= N_EDGES) return;
    if (g_is64) {
        const long long* p = (const long long*)ei;
        g_row[e] = (int)p[e];
        g_col[e] = (int)p[(size_t)N_EDGES + e];
    } else {
        const int* p = (const int*)ei;
        g_row[e] = p[e];
        g_col[e] = p[N_EDGES + e];
    }
}

__global__ void k_zero_agg() {
    size_t i = (size_t)blockIdx.x * blockDim.x + threadIdx.x;
    if (i < (size_t)N_NODES * D) g_agg[i] = 0.0f;
}

// ---------------- edge layer 1: h = silu([x[r]|x[c]|ea] @ eW1 + eb1) --------
// W1 (272x128 fp32, 139KB) resident in smem, persistent blocks.
// Tile: 64 edges x 128 outputs. 256 threads, each 8 edges x 4 outputs.
__global__ __launch_bounds__(256, 1) void k_edge1(
    const float* __restrict__ x, const float* __restrict__ ea,
    const float* __restrict__ W, const float* __restrict__ b, int ntiles)
{
    extern __shared__ float sm[];
    float* Ws = sm;                    // K1DIM * D
    float* As = sm + K1DIM * D;        // TE * K1DIM  (layout [edge][k])
    __shared__ float bs[D];

    const int tid = threadIdx.x;
    const int tx = tid & 31;           // output group (4 outputs via float4)
    const int ty = tid >> 5;           // edge group (8 edges)

    {   // stage weights once per block
        const float4* src = (const float4*)W;
        float4* dst = (float4*)Ws;
        for (int i = tid; i < K1DIM * D / 4; i += 256) dst[i] = src[i];
        if (tid < D) bs[tid] = b[tid];
    }
    __syncthreads();

    for (int tile = blockIdx.x; tile < ntiles; tile += gridDim.x) {
        const int e0 = tile * TE;
        // gather: warp ty fills edges ty*8 .. ty*8+7
        #pragma unroll
        for (int i = 0; i < 8; ++i) {
            const int el = ty * 8 + i;
            const int e = e0 + el;
            const int r = g_row[e], c = g_col[e];
            const float* xr = x + (size_t)r * D;
            const float* xc = x + (size_t)c * D;
            float* dst = As + el * K1DIM;
            #pragma unroll
            for (int j = tx; j < D; j += 32) { dst[j] = xr[j]; dst[D + j] = xc[j]; }
            if (tx < DE) dst[2 * D + tx] = ea[(size_t)e * DE + tx];
        }
        __syncthreads();

        float4 acc[8];
        #pragma unroll
        for (int m = 0; m < 8; ++m) acc[m] = make_float4(0.f, 0.f, 0.f, 0.f);
        const float* Ar = As + (ty * 8) * K1DIM;

        #pragma unroll 4
        for (int k = 0; k < K1DIM; ++k) {
            float4 bv = *(const float4*)(Ws + k * D + 4 * tx);
            #pragma unroll
            for (int m = 0; m < 8; ++m) {
                float a = Ar[m * K1DIM + k];
                acc[m].x = fmaf(a, bv.x, acc[m].x);
                acc[m].y = fmaf(a, bv.y, acc[m].y);
                acc[m].z = fmaf(a, bv.z, acc[m].z);
                acc[m].w = fmaf(a, bv.w, acc[m].w);
            }
        }

        float4 bb = *(const float4*)(bs + 4 * tx);
        #pragma unroll
        for (int m = 0; m < 8; ++m) {
            const int e = e0 + ty * 8 + m;
            float4 v = acc[m];
            v.x = silu_f(v.x + bb.x);
            v.y = silu_f(v.y + bb.y);
            v.z = silu_f(v.z + bb.z);
            v.w = silu_f(v.w + bb.w);
            *(float4*)(g_h + (size_t)e * D + 4 * tx) = v;
        }
        __syncthreads();
    }
}

// ---------------- edge layer 2 + scatter: agg[row] += silu(h @ eW2 + eb2) ---
__global__ __launch_bounds__(256, 2) void k_edge2(
    const float* __restrict__ W, const float* __restrict__ b, int ntiles)
{
    extern __shared__ float sm[];
    float* Ws = sm;              // D * D
    float* Hs = sm + D * D;      // TE * D
    __shared__ float bs[D];

    const int tid = threadIdx.x;
    const int tx = tid & 31;
    const int ty = tid >> 5;

    {
        const float4* src = (const float4*)W;
        float4* dst = (float4*)Ws;
        for (int i = tid; i < D * D / 4; i += 256) dst[i] = src[i];
        if (tid < D) bs[tid] = b[tid];
    }
    __syncthreads();

    for (int tile = blockIdx.x; tile < ntiles; tile += gridDim.x) {
        const int e0 = tile * TE;
        {   // h tile is contiguous
            const float4* src = (const float4*)(g_h + (size_t)e0 * D);
            float4* dst = (float4*)Hs;
            #pragma unroll
            for (int i = tid; i < TE * D / 4; i += 256) dst[i] = src[i];
        }
        __syncthreads();

        float4 acc[8];
        #pragma unroll
        for (int m = 0; m < 8; ++m) acc[m] = make_float4(0.f, 0.f, 0.f, 0.f);
        const float* Ar = Hs + (ty * 8) * D;

        #pragma unroll 4
        for (int k = 0; k < D; ++k) {
            float4 bv = *(const float4*)(Ws + k * D + 4 * tx);
            #pragma unroll
            for (int m = 0; m < 8; ++m) {
                float a = Ar[m * D + k];
                acc[m].x = fmaf(a, bv.x, acc[m].x);
                acc[m].y = fmaf(a, bv.y, acc[m].y);
                acc[m].z = fmaf(a, bv.z, acc[m].z);
                acc[m].w = fmaf(a, bv.w, acc[m].w);
            }
        }

        float4 bb = *(const float4*)(bs + 4 * tx);
        #pragma unroll
        for (int m = 0; m < 8; ++m) {
            const int e = e0 + ty * 8 + m;
            const int r = g_row[e];
            float4 v = acc[m];
            v.x = silu_f(v.x + bb.x);
            v.y = silu_f(v.y + bb.y);
            v.z = silu_f(v.z + bb.z);
            v.w = silu_f(v.w + bb.w);
            float* p = g_agg + (size_t)r * D + 4 * tx;
            asm volatile("red.global.add.v4.f32 [%0], {%1,%2,%3,%4};"
                         :: "l"(p), "f"(v.x), "f"(v.y), "f"(v.z), "f"(v.w)
                         : "memory");
        }
        __syncthreads();
    }
}

// ---------------- node layer 1: t = silu([x|agg] @ nW1 + nb1) ---------------
__global__ __launch_bounds__(256, 1) void k_node1(
    const float* __restrict__ x, const float* __restrict__ W,
    const float* __restrict__ b)
{
    extern __shared__ float sm[];
    float* Ws = sm;                  // K3DIM * D
    float* As = sm + K3DIM * D;      // TE * K3DIM
    __shared__ float bs[D];

    const int tid = threadIdx.x;
    const int tx = tid & 31;
    const int ty = tid >> 5;

    {
        const float4* src = (const float4*)W;
        float4* dst = (float4*)Ws;
        for (int i = tid; i < K3DIM * D / 4; i += 256) dst[i] = src[i];
        if (tid < D) bs[tid] = b[tid];
    }
    __syncthreads();

    const int n0 = blockIdx.x * TE;
    for (int idx = tid; idx < TE * D; idx += 256) {
        const int nl = idx >> 7, k = idx & 127;
        const int n = n0 + nl;
        float xv = 0.f, av = 0.f;
        if (n < N_NODES) {
            xv = x[(size_t)n * D + k];
            av = g_agg[(size_t)n * D + k];
        }
        As[nl * K3DIM + k] = xv;
        As[nl * K3DIM + D + k] = av;
    }
    __syncthreads();

    float4 acc[8];
    #pragma unroll
    for (int m = 0; m < 8; ++m) acc[m] = make_float4(0.f, 0.f, 0.f, 0.f);
    const float* Ar = As + (ty * 8) * K3DIM;

    #pragma unroll 4
    for (int k = 0; k < K3DIM; ++k) {
        float4 bv = *(const float4*)(Ws + k * D + 4 * tx);
        #pragma unroll
        for (int m = 0; m < 8; ++m) {
            float a = Ar[m * K3DIM + k];
            acc[m].x = fmaf(a, bv.x, acc[m].x);
            acc[m].y = fmaf(a, bv.y, acc[m].y);
            acc[m].z = fmaf(a, bv.z, acc[m].z);
            acc[m].w = fmaf(a, bv.w, acc[m].w);
        }
    }

    float4 bb = *(const float4*)(bs + 4 * tx);
    #pragma unroll
    for (int m = 0; m < 8; ++m) {
        const int n = n0 + ty * 8 + m;
        if (n < N_NODES) {
            float4 v = acc[m];
            v.x = silu_f(v.x + bb.x);
            v.y = silu_f(v.y + bb.y);
            v.z = silu_f(v.z + bb.z);
            v.w = silu_f(v.w + bb.w);
            *(float4*)(g_t + (size_t)n * D + 4 * tx) = v;
        }
    }
}

// ---------------- node layer 2 + residual: out = x + t @ nW2 + nb2 ----------
__global__ __launch_bounds__(256, 2) void k_node2(
    const float* __restrict__ x, const float* __restrict__ W,
    const float* __restrict__ b, float* __restrict__ out)
{
    extern __shared__ float sm[];
    float* Ws = sm;              // D * D
    float* Ts = sm + D * D;      // TE * D
    __shared__ float bs[D];

    const int tid = threadIdx.x;
    const int tx = tid & 31;
    const int ty = tid >> 5;

    {
        const float4* src = (const float4*)W;
        float4* dst = (float4*)Ws;
        for (int i = tid; i < D * D / 4; i += 256) dst[i] = src[i];
        if (tid < D) bs[tid] = b[tid];
    }
    __syncthreads();

    const int n0 = blockIdx.x * TE;
    for (int idx = tid; idx < TE * D; idx += 256) {
        const int nl = idx >> 7, k = idx & 127;
        const int n = n0 + nl;
        Ts[idx] = (n < N_NODES) ? g_t[(size_t)n * D + k] : 0.f;
    }
    __syncthreads();

    float4 acc[8];
    #pragma unroll
    for (int m = 0; m < 8; ++m) acc[m] = make_float4(0.f, 0.f, 0.f, 0.f);
    const float* Ar = Ts + (ty * 8) * D;

    #pragma unroll 4
    for (int k = 0; k < D; ++k) {
        float4 bv = *(const float4*)(Ws + k * D + 4 * tx);
        #pragma unroll
        for (int m = 0; m < 8; ++m) {
            float a = Ar[m * D + k];
            acc[m].x = fmaf(a, bv.x, acc[m].x);
            acc[m].y = fmaf(a, bv.y, acc[m].y);
            acc[m].z = fmaf(a, bv.z, acc[m].z);
            acc[m].w = fmaf(a, bv.w, acc[m].w);
        }
    }

    float4 bb = *(const float4*)(bs + 4 * tx);
    #pragma unroll
    for (int m = 0; m < 8; ++m) {
        const int n = n0 + ty * 8 + m;
        if (n < N_NODES) {
            float4 xv = *(const float4*)(x + (size_t)n * D + 4 * tx);
            float4 v = acc[m];
            v.x += bb.x + xv.x;
            v.y += bb.y + xv.y;
            v.z += bb.z + xv.z;
            v.w += bb.w + xv.w;
            *(float4*)(out + (size_t)n * D + 4 * tx) = v;
        }
    }
}

// ---------------- launch ----------------------------------------------------
extern "C" void kernel_launch(void* const* d_in, const int* in_sizes, int n_in,
                              void* d_out, int out_size)
{
    const float* x   = (const float*)d_in[0];
    const void*  ei  = d_in[1];
    const float* ea  = (const float*)d_in[2];
    const float* eW1 = (const float*)d_in[3];
    const float* eb1 = (const float*)d_in[4];
    const float* eW2 = (const float*)d_in[5];
    const float* eb2 = (const float*)d_in[6];
    const float* nW1 = (const float*)d_in[7];
    const float* nb1 = (const float*)d_in[8];
    const float* nW2 = (const float*)d_in[9];
    const float* nb2 = (const float*)d_in[10];
    float* out = (float*)d_out;

    const int s_e1 = (K1DIM * D + TE * K1DIM) * (int)sizeof(float);   // 208,896
    const int s_e2 = (D * D + TE * D) * (int)sizeof(float);           //  98,304
    const int s_n1 = (K3DIM * D + TE * K3DIM) * (int)sizeof(float);   // 196,608
    const int s_n2 = s_e2;

    cudaFuncSetAttribute(k_edge1, cudaFuncAttributeMaxDynamicSharedMemorySize, s_e1);
    cudaFuncSetAttribute(k_edge2, cudaFuncAttributeMaxDynamicSharedMemorySize, s_e2);
    cudaFuncSetAttribute(k_node1, cudaFuncAttributeMaxDynamicSharedMemorySize, s_n1);
    cudaFuncSetAttribute(k_node2, cudaFuncAttributeMaxDynamicSharedMemorySize, s_n2);

    const int etiles = N_EDGES / TE;                 // 12500
    const int ntiles = (N_NODES + TE - 1) / TE;      // 782

    k_detect<<<1, 1>>>((const int*)ei);
    k_convert<<<(N_EDGES + 255) / 256, 256>>>(ei);
    k_zero_agg<<<((size_t)N_NODES * D + 255) / 256, 256>>>();
    k_edge1<<<148, 256, s_e1>>>(x, ea, eW1, eb1, etiles);
    k_edge2<<<296, 256, s_e2>>>(eW2, eb2, etiles);
    k_node1<<<ntiles, 256, s_n1>>>(x, nW1, nb1);
    k_node2<<<ntiles, 256, s_n2>>>(x, nW2, nb2, out);
}

// round 4
// speedup vs baseline: 1.8116x; 1.8116x over previous
#include <cuda_runtime.h>
#include <cstdint>

#define N_NODES 50000
#define N_EDGES 800000
#define D 128
#define DE 16
#define K1 272            // 2*D + DE
#define K1PAD 288         // padded to 9 atom cols of 32 fp32
#define TM 128            // edges per tile
#define NTILES (N_EDGES / TM)   // 6250
#define K3DIM 256
#define TE 64

// W1 B-operand: [N=128 rows][K=288] tf32, blocked-atom SW128 layout
#define W1B_WORDS (128 * K1PAD)       // 36864
#define W2B_WORDS (128 * 128)         // 16384
#define W1B_BYTES (W1B_WORDS * 4)     // 147456
#define W2B_BYTES (W2B_WORDS * 4)     // 65536

// TMEM column layout (512 cols)
#define TMEM_A1 0      // 272 cols (edge_input, tf32)
#define TMEM_A2 0      // 128 cols (silu(h)) -- overwrites A1[0:128]
#define TMEM_D2 128    // 128 cols (fp32)    -- overwrites A1[128:256]
#define TMEM_D1 320    // 128 cols (fp32)

#define IDESC_TF32 0x8200910u   // dtypeF32 | aTF32(2) | bTF32(2) | N=128 | M=128

#define HAS_TCGEN05 (defined(__CUDA_ARCH__) && defined(__CUDA_ARCH_FEAT_SM103_ALL))

// ---------------- scratch -----------------------------------------------
__device__ int      g_is64;
__device__ int      g_row[N_EDGES];
__device__ int      g_col[N_EDGES];
__device__ float    g_agg[(size_t)N_NODES * D];
__device__ float    g_t[(size_t)N_NODES * D];
__device__ uint32_t g_W1B[W1B_WORDS];
__device__ uint32_t g_W2B[W2B_WORDS];

__device__ __forceinline__ float silu_f(float v) {
    return v / (1.0f + __expf(-v));
}

// ---------------- PTX helpers --------------------------------------------
__device__ __forceinline__ uint32_t smem_u32(const void* p) {
    uint32_t a;
    asm("{ .reg .u64 t; cvta.to.shared.u64 t, %1; cvt.u32.u64 %0, t; }"
        : "=r"(a) : "l"(p));
    return a;
}
__device__ __forceinline__ uint32_t f2tf32(float f) {
    uint32_t u;
    asm("cvt.rna.tf32.f32 %0, %1;" : "=r"(u) : "f"(f));
    return u;
}

#if defined(__CUDA_ARCH__) && defined(__CUDA_ARCH_FEAT_SM103_ALL)

__device__ __forceinline__ uint32_t elect_one() {
    uint32_t pred;
    asm volatile("{\n\t.reg .pred p;\n\telect.sync _|p, 0xFFFFFFFF;\n\t"
                 "selp.b32 %0, 1, 0, p;\n\t}" : "=r"(pred));
    return pred;
}

#define TC_ALLOC(smemaddr, n) \
    asm volatile("tcgen05.alloc.cta_group::1.sync.aligned.shared::cta.b32 [%0], %1;" \
                 :: "r"(smemaddr), "r"((uint32_t)(n)) : "memory")
#define TC_RELINQ() \
    asm volatile("tcgen05.relinquish_alloc_permit.cta_group::1.sync.aligned;")
#define TC_DEALLOC(tmem, n) \
    asm volatile("tcgen05.dealloc.cta_group::1.sync.aligned.b32 %0, %1;" \
                 :: "r"(tmem), "r"((uint32_t)(n)))
#define TC_WAIT_ST() asm volatile("tcgen05.wait::st.sync.aligned;" ::: "memory")
#define TC_WAIT_LD() asm volatile("tcgen05.wait::ld.sync.aligned;" ::: "memory")
#define TC_FENCE_BEFORE() asm volatile("tcgen05.fence::before_thread_sync;" ::: "memory")
#define TC_FENCE_AFTER()  asm volatile("tcgen05.fence::after_thread_sync;" ::: "memory")
#define TC_COMMIT(mbar) \
    asm volatile("tcgen05.commit.cta_group::1.mbarrier::arrive::one.shared::cluster.b64 [%0];" \
                 :: "r"(mbar) : "memory")
#define MBAR_INIT(mbar, cnt) \
    asm volatile("mbarrier.init.shared.b64 [%0], %1;" :: "r"(mbar), "r"((uint32_t)(cnt)) : "memory")

#define MBAR_WAIT(mbar, ph) do {                                             \
    uint32_t _m = (mbar), _p = (uint32_t)(ph), _d;                           \
    asm volatile("{\n\t.reg .pred p;\n\t"                                    \
        "mbarrier.try_wait.parity.acquire.cta.shared::cta.b64 p, [%1], %2;\n\t" \
        "selp.b32 %0, 1, 0, p;\n\t}" : "=r"(_d) : "r"(_m), "r"(_p) : "memory"); \
    if (!_d) {                                                               \
        asm volatile("{\n\t.reg .pred P1;\n\t"                               \
            "WL_%=:\n\t"                                                     \
            "mbarrier.try_wait.parity.acquire.cta.shared::cta.b64 P1, [%0], %1, 0x989680;\n\t" \
            "@P1 bra.uni WD_%=;\n\t"                                         \
            "bra.uni WL_%=;\n\t"                                             \
            "WD_%=:\n\t}" :: "r"(_m), "r"(_p) : "memory");                   \
    }                                                                        \
} while (0)

#define TC_MMA_TF32(dtm, atm, bdesc, en) do {                                \
    uint32_t _e = (en) ? 1u : 0u;                                            \
    asm volatile("{\n\t.reg .pred p;\n\t"                                    \
        "setp.ne.u32 p, %5, 0;\n\t"                                          \
        "tcgen05.mma.cta_group::1.kind::tf32 [%0], [%1], %2, %3, {%4, %4, %4, %4}, p;\n\t" \
        "}" :: "r"(dtm), "r"(atm), "l"(bdesc), "r"(IDESC_TF32),              \
               "r"(0u), "r"(_e) : "memory");                                 \
} while (0)

#define TC_ST_X32(tmem_addr, r)                                              \
    asm volatile("tcgen05.st.sync.aligned.32x32b.x32.b32 [%0], "             \
        "{%1, %2, %3, %4, %5, %6, %7, %8, "                                  \
        " %9, %10, %11, %12, %13, %14, %15, %16, "                           \
        " %17, %18, %19, %20, %21, %22, %23, %24, "                          \
        " %25, %26, %27, %28, %29, %30, %31, %32};"                          \
        :: "r"(tmem_addr),                                                   \
           "r"((r)[0]),  "r"((r)[1]),  "r"((r)[2]),  "r"((r)[3]),            \
           "r"((r)[4]),  "r"((r)[5]),  "r"((r)[6]),  "r"((r)[7]),            \
           "r"((r)[8]),  "r"((r)[9]),  "r"((r)[10]), "r"((r)[11]),           \
           "r"((r)[12]), "r"((r)[13]), "r"((r)[14]), "r"((r)[15]),           \
           "r"((r)[16]), "r"((r)[17]), "r"((r)[18]), "r"((r)[19]),           \
           "r"((r)[20]), "r"((r)[21]), "r"((r)[22]), "r"((r)[23]),           \
           "r"((r)[24]), "r"((r)[25]), "r"((r)[26]), "r"((r)[27]),           \
           "r"((r)[28]), "r"((r)[29]), "r"((r)[30]), "r"((r)[31])            \
        : "memory")

#define TC_ST_X16(tmem_addr, r)                                              \
    asm volatile("tcgen05.st.sync.aligned.32x32b.x16.b32 [%0], "             \
        "{%1, %2, %3, %4, %5, %6, %7, %8, "                                  \
        " %9, %10, %11, %12, %13, %14, %15, %16};"                           \
        :: "r"(tmem_addr),                                                   \
           "r"((r)[0]),  "r"((r)[1]),  "r"((r)[2]),  "r"((r)[3]),            \
           "r"((r)[4]),  "r"((r)[5]),  "r"((r)[6]),  "r"((r)[7]),            \
           "r"((r)[8]),  "r"((r)[9]),  "r"((r)[10]), "r"((r)[11]),           \
           "r"((r)[12]), "r"((r)[13]), "r"((r)[14]), "r"((r)[15])            \
        : "memory")

#define TC_LD_X32(r, tmem_addr)                                              \
    asm volatile("tcgen05.ld.sync.aligned.32x32b.x32.b32 "                   \
        "{%0, %1, %2, %3, %4, %5, %6, %7, "                                  \
        " %8, %9, %10, %11, %12, %13, %14, %15, "                            \
        " %16, %17, %18, %19, %20, %21, %22, %23, "                          \
        " %24, %25, %26, %27, %28, %29, %30, %31}, [%32];"                   \
        : "=r"((r)[0]),  "=r"((r)[1]),  "=r"((r)[2]),  "=r"((r)[3]),         \
          "=r"((r)[4]),  "=r"((r)[5]),  "=r"((r)[6]),  "=r"((r)[7]),         \
          "=r"((r)[8]),  "=r"((r)[9]),  "=r"((r)[10]), "=r"((r)[11]),        \
          "=r"((r)[12]), "=r"((r)[13]), "=r"((r)[14]), "=r"((r)[15]),        \
          "=r"((r)[16]), "=r"((r)[17]), "=r"((r)[18]), "=r"((r)[19]),        \
          "=r"((r)[20]), "=r"((r)[21]), "=r"((r)[22]), "=r"((r)[23]),        \
          "=r"((r)[24]), "=r"((r)[25]), "=r"((r)[26]), "=r"((r)[27]),        \
          "=r"((r)[28]), "=r"((r)[29]), "=r"((r)[30]), "=r"((r)[31])         \
        : "r"(tmem_addr))

static constexpr unsigned long long SMEM_DESC_BASE =
    (2ull << 61) | (1ull << 46) | (64ull << 32) | (1ull << 16);

__device__ __forceinline__ uint64_t mk_desc(uint32_t addr) {
    return SMEM_DESC_BASE | ((uint64_t)(addr >> 4) & 0x3FFF);
}
// K-step s (8 tf32 = 32 B): offset in 16B units within blocked-atom layout
// (16 atom rows for N=128 -> atom-col stride = 16*1024 B = 1024 units)
__device__ __forceinline__ uint64_t koff(int s) {
    return (uint64_t)((s >> 2) * 1024 + (s & 3) * 2);
}

#endif // sm_103a feature guard (device helpers)

// ---------------- index conversion --------------------------------------
__global__ void k_detect(const int* ei32) {
    if (blockIdx.x == 0 && threadIdx.x == 0) {
        int is64 = 1;
        #pragma unroll 1
        for (int i = 0; i < 64; ++i)
            if (ei32[2 * i + 1] != 0) { is64 = 0; break; }
        g_is64 = is64;
    }
}
__global__ void k_convert(const void* ei) {
    int e = blockIdx.x * blockDim.x + threadIdx.x;
    if (e >= N_EDGES) return;
    if (g_is64) {
        const long long* p = (const long long*)ei;
        g_row[e] = (int)p[e];
        g_col[e] = (int)p[(size_t)N_EDGES + e];
    } else {
        const int* p = (const int*)ei;
        g_row[e] = p[e];
        g_col[e] = p[N_EDGES + e];
    }
}
__global__ void k_zero_agg() {
    size_t i = (size_t)blockIdx.x * blockDim.x + threadIdx.x;
    if (i < (size_t)N_NODES * D) g_agg[i] = 0.0f;
}

// ---------------- weight prep: transpose+tf32+blocked-atom SW128 --------
__global__ void k_prepW1(const float* __restrict__ W1) {
    int i = blockIdx.x * blockDim.x + threadIdx.x;   // over 128*288
    if (i >= W1B_WORDS) return;
    int n = i / K1PAD, k = i % K1PAD;
    float v = (k < K1) ? W1[(size_t)k * 128 + n] : 0.0f;
    int atom_off = (n >> 3) + (k >> 5) * 16;
    uint32_t byte = atom_off * 1024 + (n & 7) * 128 + (k & 31) * 4;
    uint32_t sw = byte ^ ((byte >> 3) & 0x70);
    g_W1B[sw >> 2] = f2tf32(v);
}
__global__ void k_prepW2(const float* __restrict__ W2) {
    int i = blockIdx.x * blockDim.x + threadIdx.x;   // over 128*128
    if (i >= W2B_WORDS) return;
    int n = i / 128, k = i % 128;
    float v = W2[(size_t)k * 128 + n];
    int atom_off = (n >> 3) + (k >> 5) * 16;
    uint32_t byte = atom_off * 1024 + (n & 7) * 128 + (k & 31) * 4;
    uint32_t sw = byte ^ ((byte >> 3) & 0x70);
    g_W2B[sw >> 2] = f2tf32(v);
}

// ---------------- fused edge kernel (tcgen05 tf32 on sm_103a) -------------
__global__ __launch_bounds__(128, 1) void k_edge_fused(
    const float* __restrict__ x, const float* __restrict__ ea,
    const float* __restrict__ eb1, const float* __restrict__ eb2,
    const float* __restrict__ eW1raw, const float* __restrict__ eW2raw)
{
#if defined(__CUDA_ARCH__) && defined(__CUDA_ARCH_FEAT_SM103_ALL)
    extern __shared__ uint32_t dsm[];
    __shared__ float s_eb1[D], s_eb2[D];
    __shared__ uint32_t s_tmem[1];
    __shared__ __align__(8) unsigned long long s_mbar;

    const int tid = threadIdx.x;
    const int wid = tid >> 5;
    const uint32_t woff = (uint32_t)wid << 21;

    const uint32_t dyn_base = smem_u32(dsm);
    const uint32_t ws1 = (dyn_base + 1023u) & ~1023u;
    const uint32_t ws2 = ws1 + W1B_BYTES;
    uint32_t* w1p = dsm + ((ws1 - dyn_base) >> 2);
    uint32_t* w2p = w1p + W1B_WORDS;

    // stage weights (swizzle pre-baked) + biases
    {
        uint4* d1 = (uint4*)w1p; const uint4* s1 = (const uint4*)g_W1B;
        for (int i = tid; i < W1B_WORDS / 4; i += 128) d1[i] = s1[i];
        uint4* d2 = (uint4*)w2p; const uint4* s2 = (const uint4*)g_W2B;
        for (int i = tid; i < W2B_WORDS / 4; i += 128) d2[i] = s2[i];
        if (tid < D) { s_eb1[tid] = eb1[tid]; s_eb2[tid] = eb2[tid]; }
    }

    if (wid == 0) TC_ALLOC(smem_u32(s_tmem), 512);
    if (tid == 0) MBAR_INIT(smem_u32(&s_mbar), 1);
    __syncthreads();
    const uint32_t tbase = s_tmem[0];
    const uint32_t mbar = smem_u32(&s_mbar);
    const uint64_t w1d = mk_desc(ws1);
    const uint64_t w2d = mk_desc(ws2);

    int phase = 0;
    for (int tile = blockIdx.x; tile < NTILES; tile += gridDim.x) {
        const int e = tile * TM + tid;
        const int r = g_row[e], c = g_col[e];

        // ---- gather edge_input row -> TMEM A1 (tf32) ----
        {
            uint32_t a[32];
            const float4* xr = (const float4*)(x + (size_t)r * D);
            #pragma unroll
            for (int ch = 0; ch < 4; ++ch) {
                #pragma unroll
                for (int q = 0; q < 8; ++q) {
                    float4 v = xr[ch * 8 + q];
                    a[q*4+0] = f2tf32(v.x); a[q*4+1] = f2tf32(v.y);
                    a[q*4+2] = f2tf32(v.z); a[q*4+3] = f2tf32(v.w);
                }
                TC_ST_X32(tbase + TMEM_A1 + ch * 32 + woff, a);
            }
            const float4* xc = (const float4*)(x + (size_t)c * D);
            #pragma unroll
            for (int ch = 0; ch < 4; ++ch) {
                #pragma unroll
                for (int q = 0; q < 8; ++q) {
                    float4 v = xc[ch * 8 + q];
                    a[q*4+0] = f2tf32(v.x); a[q*4+1] = f2tf32(v.y);
                    a[q*4+2] = f2tf32(v.z); a[q*4+3] = f2tf32(v.w);
                }
                TC_ST_X32(tbase + TMEM_A1 + 128 + ch * 32 + woff, a);
            }
            const float4* ep = (const float4*)(ea + (size_t)e * DE);
            #pragma unroll
            for (int q = 0; q < 4; ++q) {
                float4 v = ep[q];
                a[q*4+0] = f2tf32(v.x); a[q*4+1] = f2tf32(v.y);
                a[q*4+2] = f2tf32(v.z); a[q*4+3] = f2tf32(v.w);
            }
            TC_ST_X16(tbase + TMEM_A1 + 256 + woff, a);
        }
        TC_WAIT_ST();
        TC_FENCE_BEFORE();
        __syncthreads();

        // ---- MMA1: D1 = A1 @ W1  (K = 272 = 34 steps of 8) ----
        if (wid == 0) {
            TC_FENCE_AFTER();
            if (elect_one()) {
                #pragma unroll 1
                for (int s = 0; s < 34; ++s)
                    TC_MMA_TF32(tbase + TMEM_D1, tbase + TMEM_A1 + s * 8,
                                w1d + koff(s), s > 0);
                TC_COMMIT(mbar);
            }
        }
        MBAR_WAIT(mbar, phase); phase ^= 1;
        TC_FENCE_AFTER();

        // ---- D1 -> bias+silu -> A2 (tf32) ----
        #pragma unroll 1
        for (int ch = 0; ch < 4; ++ch) {
            uint32_t dreg[32], areg[32];
            TC_LD_X32(dreg, tbase + TMEM_D1 + ch * 32);
            TC_WAIT_LD();
            #pragma unroll
            for (int j = 0; j < 32; ++j) {
                float v = __uint_as_float(dreg[j]) + s_eb1[ch * 32 + j];
                areg[j] = f2tf32(silu_f(v));
            }
            TC_ST_X32(tbase + TMEM_A2 + ch * 32 + woff, areg);
        }
        TC_WAIT_ST();
        TC_FENCE_BEFORE();
        __syncthreads();

        // ---- MMA2: D2 = A2 @ W2  (K = 128 = 16 steps) ----
        if (wid == 0) {
            TC_FENCE_AFTER();
            if (elect_one()) {
                #pragma unroll 1
                for (int s = 0; s < 16; ++s)
                    TC_MMA_TF32(tbase + TMEM_D2, tbase + TMEM_A2 + s * 8,
                                w2d + koff(s), s > 0);
                TC_COMMIT(mbar);
            }
        }
        MBAR_WAIT(mbar, phase); phase ^= 1;
        TC_FENCE_AFTER();

        // ---- D2 -> bias+silu -> scatter-add to g_agg[row] ----
        {
            float* aggp = g_agg + (size_t)r * D;
            #pragma unroll 1
            for (int ch = 0; ch < 4; ++ch) {
                uint32_t dreg[32];
                TC_LD_X32(dreg, tbase + TMEM_D2 + ch * 32);
                TC_WAIT_LD();
                #pragma unroll
                for (int q = 0; q < 8; ++q) {
                    float v0 = silu_f(__uint_as_float(dreg[q*4+0]) + s_eb2[ch*32+q*4+0]);
                    float v1 = silu_f(__uint_as_float(dreg[q*4+1]) + s_eb2[ch*32+q*4+1]);
                    float v2 = silu_f(__uint_as_float(dreg[q*4+2]) + s_eb2[ch*32+q*4+2]);
                    float v3 = silu_f(__uint_as_float(dreg[q*4+3]) + s_eb2[ch*32+q*4+3]);
                    asm volatile("red.global.add.v4.f32 [%0], {%1,%2,%3,%4};"
                                 :: "l"(aggp + ch * 32 + q * 4),
                                    "f"(v0), "f"(v1), "f"(v2), "f"(v3) : "memory");
                }
            }
        }
        __syncthreads();
    }

    __syncthreads();
    if (wid == 0) { TC_RELINQ(); TC_DEALLOC(tbase, 512); }

#else
    // ---- plain-sm_103 fallback (correct, slow; never selected on GB300 — the
    // driver loads the sm_103a cubin). One thread per edge, direct global W.
    const int tid = threadIdx.x;
    for (int tile = blockIdx.x; tile < NTILES; tile += gridDim.x) {
        const int e = tile * TM + tid;
        const int r = g_row[e], c = g_col[e];
        float a[K1];
        #pragma unroll 4
        for (int j = 0; j < D; ++j) { a[j] = x[(size_t)r * D + j]; a[D + j] = x[(size_t)c * D + j]; }
        #pragma unroll
        for (int j = 0; j < DE; ++j) a[2 * D + j] = ea[(size_t)e * DE + j];
        float h[D];
        for (int n = 0; n < D; ++n) {
            float s = eb1[n];
            for (int k = 0; k < K1; ++k) s = fmaf(a[k], eW1raw[(size_t)k * D + n], s);
            h[n] = silu_f(s);
        }
        for (int n = 0; n < D; ++n) {
            float s = eb2[n];
            for (int k = 0; k < D; ++k) s = fmaf(h[k], eW2raw[(size_t)k * D + n], s);
            atomicAdd(g_agg + (size_t)r * D + n, silu_f(s));
        }
    }
#endif
}

// ---------------- node layer 1: t = silu([x|agg] @ nW1 + nb1) -----------
__global__ __launch_bounds__(256, 1) void k_node1(
    const float* __restrict__ x, const float* __restrict__ W,
    const float* __restrict__ b)
{
    extern __shared__ float sm[];
    float* Ws = sm;
    float* As = sm + K3DIM * D;
    __shared__ float bs[D];

    const int tid = threadIdx.x;
    const int tx = tid & 31;
    const int ty = tid >> 5;
    {
        const float4* src = (const float4*)W;
        float4* dst = (float4*)Ws;
        for (int i = tid; i < K3DIM * D / 4; i += 256) dst[i] = src[i];
        if (tid < D) bs[tid] = b[tid];
    }
    __syncthreads();

    const int n0 = blockIdx.x * TE;
    for (int idx = tid; idx < TE * D; idx += 256) {
        const int nl = idx >> 7, k = idx & 127;
        const int n = n0 + nl;
        float xv = 0.f, av = 0.f;
        if (n < N_NODES) {
            xv = x[(size_t)n * D + k];
            av = g_agg[(size_t)n * D + k];
        }
        As[nl * K3DIM + k] = xv;
        As[nl * K3DIM + D + k] = av;
    }
    __syncthreads();

    float4 acc[8];
    #pragma unroll
    for (int m = 0; m < 8; ++m) acc[m] = make_float4(0.f, 0.f, 0.f, 0.f);
    const float* Ar = As + (ty * 8) * K3DIM;
    #pragma unroll 4
    for (int k = 0; k < K3DIM; ++k) {
        float4 bv = *(const float4*)(Ws + k * D + 4 * tx);
        #pragma unroll
        for (int m = 0; m < 8; ++m) {
            float a = Ar[m * K3DIM + k];
            acc[m].x = fmaf(a, bv.x, acc[m].x);
            acc[m].y = fmaf(a, bv.y, acc[m].y);
            acc[m].z = fmaf(a, bv.z, acc[m].z);
            acc[m].w = fmaf(a, bv.w, acc[m].w);
        }
    }
    float4 bb = *(const float4*)(bs + 4 * tx);
    #pragma unroll
    for (int m = 0; m < 8; ++m) {
        const int n = n0 + ty * 8 + m;
        if (n < N_NODES) {
            float4 v = acc[m];
            v.x = silu_f(v.x + bb.x);
            v.y = silu_f(v.y + bb.y);
            v.z = silu_f(v.z + bb.z);
            v.w = silu_f(v.w + bb.w);
            *(float4*)(g_t + (size_t)n * D + 4 * tx) = v;
        }
    }
}

// ---------------- node layer 2 + residual --------------------------------
__global__ __launch_bounds__(256, 2) void k_node2(
    const float* __restrict__ x, const float* __restrict__ W,
    const float* __restrict__ b, float* __restrict__ out)
{
    extern __shared__ float sm[];
    float* Ws = sm;
    float* Ts = sm + D * D;
    __shared__ float bs[D];

    const int tid = threadIdx.x;
    const int tx = tid & 31;
    const int ty = tid >> 5;
    {
        const float4* src = (const float4*)W;
        float4* dst = (float4*)Ws;
        for (int i = tid; i < D * D / 4; i += 256) dst[i] = src[i];
        if (tid < D) bs[tid] = b[tid];
    }
    __syncthreads();

    const int n0 = blockIdx.x * TE;
    for (int idx = tid; idx < TE * D; idx += 256) {
        const int nl = idx >> 7, k = idx & 127;
        const int n = n0 + nl;
        Ts[idx] = (n < N_NODES) ? g_t[(size_t)n * D + k] : 0.f;
    }
    __syncthreads();

    float4 acc[8];
    #pragma unroll
    for (int m = 0; m < 8; ++m) acc[m] = make_float4(0.f, 0.f, 0.f, 0.f);
    const float* Ar = Ts + (ty * 8) * D;
    #pragma unroll 4
    for (int k = 0; k < D; ++k) {
        float4 bv = *(const float4*)(Ws + k * D + 4 * tx);
        #pragma unroll
        for (int m = 0; m < 8; ++m) {
            float a = Ar[m * D + k];
            acc[m].x = fmaf(a, bv.x, acc[m].x);
            acc[m].y = fmaf(a, bv.y, acc[m].y);
            acc[m].z = fmaf(a, bv.z, acc[m].z);
            acc[m].w = fmaf(a, bv.w, acc[m].w);
        }
    }
    float4 bb = *(const float4*)(bs + 4 * tx);
    #pragma unroll
    for (int m = 0; m < 8; ++m) {
        const int n = n0 + ty * 8 + m;
        if (n < N_NODES) {
            float4 xv = *(const float4*)(x + (size_t)n * D + 4 * tx);
            float4 v = acc[m];
            v.x += bb.x + xv.x;
            v.y += bb.y + xv.y;
            v.z += bb.z + xv.z;
            v.w += bb.w + xv.w;
            *(float4*)(out + (size_t)n * D + 4 * tx) = v;
        }
    }
}

// ---------------- launch --------------------------------------------------
extern "C" void kernel_launch(void* const* d_in, const int* in_sizes, int n_in,
                              void* d_out, int out_size)
{
    const float* x   = (const float*)d_in[0];
    const void*  ei  = d_in[1];
    const float* ea  = (const float*)d_in[2];
    const float* eW1 = (const float*)d_in[3];
    const float* eb1 = (const float*)d_in[4];
    const float* eW2 = (const float*)d_in[5];
    const float* eb2 = (const float*)d_in[6];
    const float* nW1 = (const float*)d_in[7];
    const float* nb1 = (const float*)d_in[8];
    const float* nW2 = (const float*)d_in[9];
    const float* nb2 = (const float*)d_in[10];
    float* out = (float*)d_out;

    const int s_edge = 1024 + W1B_BYTES + W2B_BYTES;                 // 214,016
    const int s_n1 = (K3DIM * D + TE * K3DIM) * (int)sizeof(float);  // 196,608
    const int s_n2 = (D * D + TE * D) * (int)sizeof(float);          //  98,304

    cudaFuncSetAttribute(k_edge_fused, cudaFuncAttributeMaxDynamicSharedMemorySize, s_edge);
    cudaFuncSetAttribute(k_node1, cudaFuncAttributeMaxDynamicSharedMemorySize, s_n1);
    cudaFuncSetAttribute(k_node2, cudaFuncAttributeMaxDynamicSharedMemorySize, s_n2);

    const int ntiles = (N_NODES + TE - 1) / TE;

    k_detect<<<1, 1>>>((const int*)ei);
    k_convert<<<(N_EDGES + 255) / 256, 256>>>(ei);
    k_zero_agg<<<((size_t)N_NODES * D + 255) / 256, 256>>>();
    k_prepW1<<<(W1B_WORDS + 255) / 256, 256>>>(eW1);
    k_prepW2<<<(W2B_WORDS + 255) / 256, 256>>>(eW2);
    k_edge_fused<<<152, 128, s_edge>>>(x, ea, eb1, eb2, eW1, eW2);
    k_node1<<<ntiles, 256, s_n1>>>(x, nW1, nb1);
    k_node2<<<ntiles, 256, s_n2>>>(x, nW2, nb2, out);
}

// round 5
// speedup vs baseline: 2.0321x; 1.1217x over previous
#include <cuda_runtime.h>
#include <cuda_bf16.h>
#include <cstdint>

#define N_NODES 50000
#define N_EDGES 800000
#define D 128
#define DE 16
#define K1 272            // 2*D + DE
#define K1PAD 320         // padded to 5 SW128 atom cols of 64 bf16
#define TM 128            // edges per tile
#define NTILES (N_EDGES / TM)   // 6250
#define K3DIM 256
#define TE 64

// B operands (bf16, blocked-atom SW128, N=128 rows => 16 atom rows)
#define W1B_BYTES (128 * K1PAD * 2)   // 81920
#define W2B_BYTES (128 * 128 * 2)     // 32768

// TMEM columns (bf16 A packs 2 K-elems per col)
#define TMEM_A1_0 0        // 136 cols buf0
#define TMEM_A1_1 136      // 136 cols buf1
#define TMEM_DD   272      // 128 cols fp32 (shared D1/D2)
#define TMEM_A2   400      // 64 cols bf16

#define IDESC_BF16 0x8200490u   // F32 acc | aBF16 | bBF16 | N=128 | M=128

// ---------------- scratch -----------------------------------------------
__device__ int      g_is64;
__device__ int      g_row[N_EDGES];
__device__ int      g_col[N_EDGES];
__device__ float    g_agg[(size_t)N_NODES * D];
__device__ float    g_t[(size_t)N_NODES * D];
__device__ uint16_t g_W1B[W1B_BYTES / 2];
__device__ uint16_t g_W2B[W2B_BYTES / 2];

__device__ __forceinline__ float silu_f(float v) {
    return v / (1.0f + __expf(-v));
}
__device__ __forceinline__ uint32_t smem_u32(const void* p) {
    uint32_t a;
    asm("{ .reg .u64 t; cvta.to.shared.u64 t, %1; cvt.u32.u64 %0, t; }"
        : "=r"(a) : "l"(p));
    return a;
}
__device__ __forceinline__ uint32_t pack_bf16x2(float lo, float hi) {
    uint32_t d;
    asm("cvt.rn.bf16x2.f32 %0, %1, %2;" : "=r"(d) : "f"(hi), "f"(lo));
    return d;
}
__device__ __forceinline__ uint16_t bf16_bits(float v) {
    __nv_bfloat16 b = __float2bfloat16(v);
    return *reinterpret_cast<uint16_t*>(&b);
}

#if defined(__CUDA_ARCH__) && defined(__CUDA_ARCH_FEAT_SM103_ALL)

__device__ __forceinline__ uint32_t elect_one() {
    uint32_t pred;
    asm volatile("{\n\t.reg .pred p;\n\telect.sync _|p, 0xFFFFFFFF;\n\t"
                 "selp.b32 %0, 1, 0, p;\n\t}" : "=r"(pred));
    return pred;
}

#define TC_ALLOC(smemaddr, n) \
    asm volatile("tcgen05.alloc.cta_group::1.sync.aligned.shared::cta.b32 [%0], %1;" \
                 :: "r"(smemaddr), "r"((uint32_t)(n)) : "memory")
#define TC_RELINQ() \
    asm volatile("tcgen05.relinquish_alloc_permit.cta_group::1.sync.aligned;")
#define TC_DEALLOC(tmem, n) \
    asm volatile("tcgen05.dealloc.cta_group::1.sync.aligned.b32 %0, %1;" \
                 :: "r"(tmem), "r"((uint32_t)(n)))
#define TC_WAIT_ST() asm volatile("tcgen05.wait::st.sync.aligned;" ::: "memory")
#define TC_WAIT_LD() asm volatile("tcgen05.wait::ld.sync.aligned;" ::: "memory")
#define TC_FENCE_BEFORE() asm volatile("tcgen05.fence::before_thread_sync;" ::: "memory")
#define TC_FENCE_AFTER()  asm volatile("tcgen05.fence::after_thread_sync;" ::: "memory")
#define TC_COMMIT(mbar) \
    asm volatile("tcgen05.commit.cta_group::1.mbarrier::arrive::one.shared::cluster.b64 [%0];" \
                 :: "r"(mbar) : "memory")
#define MBAR_INIT(mbar, cnt) \
    asm volatile("mbarrier.init.shared.b64 [%0], %1;" :: "r"(mbar), "r"((uint32_t)(cnt)) : "memory")

#define MBAR_WAIT(mbar, ph) do {                                             \
    uint32_t _m = (mbar), _p = (uint32_t)(ph), _d;                           \
    asm volatile("{\n\t.reg .pred p;\n\t"                                    \
        "mbarrier.try_wait.parity.acquire.cta.shared::cta.b64 p, [%1], %2;\n\t" \
        "selp.b32 %0, 1, 0, p;\n\t}" : "=r"(_d) : "r"(_m), "r"(_p) : "memory"); \
    if (!_d) {                                                               \
        asm volatile("{\n\t.reg .pred P1;\n\t"                               \
            "WL_%=:\n\t"                                                     \
            "mbarrier.try_wait.parity.acquire.cta.shared::cta.b64 P1, [%0], %1, 0x989680;\n\t" \
            "@P1 bra.uni WD_%=;\n\t"                                         \
            "bra.uni WL_%=;\n\t"                                             \
            "WD_%=:\n\t}" :: "r"(_m), "r"(_p) : "memory");                   \
    }                                                                        \
} while (0)

#define TC_MMA_BF16(dtm, atm, bdesc, en) do {                                \
    uint32_t _e = (en) ? 1u : 0u;                                            \
    asm volatile("{\n\t.reg .pred p;\n\t"                                    \
        "setp.ne.u32 p, %5, 0;\n\t"                                          \
        "tcgen05.mma.cta_group::1.kind::f16 [%0], [%1], %2, %3, {%4, %4, %4, %4}, p;\n\t" \
        "}" :: "r"(dtm), "r"(atm), "l"(bdesc), "r"(IDESC_BF16),              \
               "r"(0u), "r"(_e) : "memory");                                 \
} while (0)

#define TC_ST_X32(tmem_addr, r)                                              \
    asm volatile("tcgen05.st.sync.aligned.32x32b.x32.b32 [%0], "             \
        "{%1, %2, %3, %4, %5, %6, %7, %8, "                                  \
        " %9, %10, %11, %12, %13, %14, %15, %16, "                           \
        " %17, %18, %19, %20, %21, %22, %23, %24, "                          \
        " %25, %26, %27, %28, %29, %30, %31, %32};"                          \
        :: "r"(tmem_addr),                                                   \
           "r"((r)[0]),  "r"((r)[1]),  "r"((r)[2]),  "r"((r)[3]),            \
           "r"((r)[4]),  "r"((r)[5]),  "r"((r)[6]),  "r"((r)[7]),            \
           "r"((r)[8]),  "r"((r)[9]),  "r"((r)[10]), "r"((r)[11]),           \
           "r"((r)[12]), "r"((r)[13]), "r"((r)[14]), "r"((r)[15]),           \
           "r"((r)[16]), "r"((r)[17]), "r"((r)[18]), "r"((r)[19]),           \
           "r"((r)[20]), "r"((r)[21]), "r"((r)[22]), "r"((r)[23]),           \
           "r"((r)[24]), "r"((r)[25]), "r"((r)[26]), "r"((r)[27]),           \
           "r"((r)[28]), "r"((r)[29]), "r"((r)[30]), "r"((r)[31])            \
        : "memory")

#define TC_ST_X16(tmem_addr, r)                                              \
    asm volatile("tcgen05.st.sync.aligned.32x32b.x16.b32 [%0], "             \
        "{%1, %2, %3, %4, %5, %6, %7, %8, "                                  \
        " %9, %10, %11, %12, %13, %14, %15, %16};"                           \
        :: "r"(tmem_addr),                                                   \
           "r"((r)[0]),  "r"((r)[1]),  "r"((r)[2]),  "r"((r)[3]),            \
           "r"((r)[4]),  "r"((r)[5]),  "r"((r)[6]),  "r"((r)[7]),            \
           "r"((r)[8]),  "r"((r)[9]),  "r"((r)[10]), "r"((r)[11]),           \
           "r"((r)[12]), "r"((r)[13]), "r"((r)[14]), "r"((r)[15])            \
        : "memory")

#define TC_ST_X8(tmem_addr, r)                                               \
    asm volatile("tcgen05.st.sync.aligned.32x32b.x8.b32 [%0], "              \
        "{%1, %2, %3, %4, %5, %6, %7, %8};"                                  \
        :: "r"(tmem_addr),                                                   \
           "r"((r)[0]), "r"((r)[1]), "r"((r)[2]), "r"((r)[3]),               \
           "r"((r)[4]), "r"((r)[5]), "r"((r)[6]), "r"((r)[7])                \
        : "memory")

#define TC_LD_X32(r, tmem_addr)                                              \
    asm volatile("tcgen05.ld.sync.aligned.32x32b.x32.b32 "                   \
        "{%0, %1, %2, %3, %4, %5, %6, %7, "                                  \
        " %8, %9, %10, %11, %12, %13, %14, %15, "                            \
        " %16, %17, %18, %19, %20, %21, %22, %23, "                          \
        " %24, %25, %26, %27, %28, %29, %30, %31}, [%32];"                   \
        : "=r"((r)[0]),  "=r"((r)[1]),  "=r"((r)[2]),  "=r"((r)[3]),         \
          "=r"((r)[4]),  "=r"((r)[5]),  "=r"((r)[6]),  "=r"((r)[7]),         \
          "=r"((r)[8]),  "=r"((r)[9]),  "=r"((r)[10]), "=r"((r)[11]),        \
          "=r"((r)[12]), "=r"((r)[13]), "=r"((r)[14]), "=r"((r)[15]),        \
          "=r"((r)[16]), "=r"((r)[17]), "=r"((r)[18]), "=r"((r)[19]),        \
          "=r"((r)[20]), "=r"((r)[21]), "=r"((r)[22]), "=r"((r)[23]),        \
          "=r"((r)[24]), "=r"((r)[25]), "=r"((r)[26]), "=r"((r)[27]),        \
          "=r"((r)[28]), "=r"((r)[29]), "=r"((r)[30]), "=r"((r)[31])         \
        : "r"(tmem_addr))

static constexpr unsigned long long SMEM_DESC_BASE =
    (2ull << 61) | (1ull << 46) | (64ull << 32) | (1ull << 16);
__device__ __forceinline__ uint64_t mk_desc(uint32_t addr) {
    return SMEM_DESC_BASE | ((uint64_t)(addr >> 4) & 0x3FFF);
}
// K-step s = 16 bf16 = 32 B. atom col = s>>2 (64 elems per SW128 atom col),
// within-atom offset (s&3)*32B = 2 units; atom-col stride = 16 atoms * 1024B = 1024 units.
__device__ __forceinline__ uint64_t koff(int s) {
    return (uint64_t)((s >> 2) * 1024 + (s & 3) * 2);
}

#endif // sm_103a device helpers

// ---------------- small kernels ------------------------------------------
__global__ void k_detect(const int* ei32) {
    if (blockIdx.x == 0 && threadIdx.x == 0) {
        int is64 = 1;
        #pragma unroll 1
        for (int i = 0; i < 64; ++i)
            if (ei32[2 * i + 1] != 0) { is64 = 0; break; }
        g_is64 = is64;
    }
}
// convert indices AND zero agg (covers max(N_EDGES, N_NODES*D) = 6.4M)
__global__ void k_convert_zero(const void* ei) {
    size_t i = (size_t)blockIdx.x * blockDim.x + threadIdx.x;
    if (i < N_EDGES) {
        if (g_is64) {
            const long long* p = (const long long*)ei;
            g_row[i] = (int)p[i];
            g_col[i] = (int)p[(size_t)N_EDGES + i];
        } else {
            const int* p = (const int*)ei;
            g_row[i] = p[i];
            g_col[i] = p[N_EDGES + i];
        }
    }
    if (i < (size_t)N_NODES * D) g_agg[i] = 0.0f;
}
// weight prep: transpose + bf16 + blocked-atom SW128 (both W1 and W2)
__global__ void k_prep(const float* __restrict__ W1, const float* __restrict__ W2) {
    int i = blockIdx.x * blockDim.x + threadIdx.x;
    if (i < 128 * K1PAD) {
        int n = i / K1PAD, k = i % K1PAD;
        float v = (k < K1) ? W1[(size_t)k * 128 + n] : 0.0f;
        int atom = (n >> 3) + (k >> 6) * 16;
        uint32_t byte = atom * 1024 + (n & 7) * 128 + (k & 63) * 2;
        uint32_t sw = byte ^ ((byte >> 3) & 0x70);
        g_W1B[sw >> 1] = bf16_bits(v);
    } else {
        i -= 128 * K1PAD;
        if (i >= 128 * 128) return;
        int n = i / 128, k = i % 128;
        float v = W2[(size_t)k * 128 + n];
        int atom = (n >> 3) + (k >> 6) * 16;
        uint32_t byte = atom * 1024 + (n & 7) * 128 + (k & 63) * 2;
        uint32_t sw = byte ^ ((byte >> 3) & 0x70);
        g_W2B[sw >> 1] = bf16_bits(v);
    }
}

// ---------------- fused edge kernel (tcgen05 bf16, prefetch-pipelined) ----
__global__ __launch_bounds__(128, 1) void k_edge_fused(
    const float* __restrict__ x, const float* __restrict__ ea,
    const float* __restrict__ eb1, const float* __restrict__ eb2,
    const float* __restrict__ eW1raw, const float* __restrict__ eW2raw,
    int nblocks)
{
#if defined(__CUDA_ARCH__) && defined(__CUDA_ARCH_FEAT_SM103_ALL)
    extern __shared__ uint32_t dsm[];
    __shared__ float s_eb1[D], s_eb2[D];
    __shared__ uint32_t s_tmem[1];
    __shared__ __align__(8) unsigned long long s_mbar;

    const int tid = threadIdx.x;
    const int wid = tid >> 5;
    const uint32_t woff = (uint32_t)wid << 21;

    const uint32_t dyn_base = smem_u32(dsm);
    const uint32_t ws1 = (dyn_base + 1023u) & ~1023u;
    const uint32_t ws2 = ws1 + W1B_BYTES;
    uint32_t* w1p = dsm + ((ws1 - dyn_base) >> 2);

    {   // stage pre-swizzled weights + biases
        uint4* d1 = (uint4*)w1p; const uint4* s1 = (const uint4*)g_W1B;
        for (int i = tid; i < (W1B_BYTES + W2B_BYTES) / 16; i += 128) d1[i] = s1[i];
        if (tid < D) { s_eb1[tid] = eb1[tid]; s_eb2[tid] = eb2[tid]; }
    }
    if (wid == 0) TC_ALLOC(smem_u32(s_tmem), 512);
    if (tid == 0) MBAR_INIT(smem_u32(&s_mbar), 1);
    __syncthreads();
    const uint32_t tbase = s_tmem[0];
    const uint32_t mbar = smem_u32(&s_mbar);
    const uint64_t w1d = mk_desc(ws1);
    const uint64_t w2d = mk_desc(ws2);

    // gather one edge-row into TMEM A1 buffer (bf16 packed)
    auto gather = [&](int tile, int buf) {
        const uint32_t abase = tbase + (buf ? TMEM_A1_1 : TMEM_A1_0) + woff;
        const int e = tile * TM + tid;
        const int r = g_row[e], c = g_col[e];
        uint32_t w[32];
        const float4* xr = (const float4*)(x + (size_t)r * D);
        #pragma unroll
        for (int part = 0; part < 2; ++part) {
            #pragma unroll
            for (int q = 0; q < 16; ++q) {
                float4 v = xr[part * 16 + q];
                w[2*q]   = pack_bf16x2(v.x, v.y);
                w[2*q+1] = pack_bf16x2(v.z, v.w);
            }
            TC_ST_X32(abase + part * 32, w);
        }
        const float4* xc = (const float4*)(x + (size_t)c * D);
        #pragma unroll
        for (int part = 0; part < 2; ++part) {
            #pragma unroll
            for (int q = 0; q < 16; ++q) {
                float4 v = xc[part * 16 + q];
                w[2*q]   = pack_bf16x2(v.x, v.y);
                w[2*q+1] = pack_bf16x2(v.z, v.w);
            }
            TC_ST_X32(abase + 64 + part * 32, w);
        }
        const float4* ep = (const float4*)(ea + (size_t)e * DE);
        #pragma unroll
        for (int q = 0; q < 4; ++q) {
            float4 v = ep[q];
            w[2*q]   = pack_bf16x2(v.x, v.y);
            w[2*q+1] = pack_bf16x2(v.z, v.w);
        }
        TC_ST_X8(abase + 128, w);
        TC_WAIT_ST();
    };

    int tile = blockIdx.x;
    int buf = 0, ph = 0;
    if (tile < NTILES) gather(tile, 0);
    TC_FENCE_BEFORE();
    __syncthreads();

    for (; tile < NTILES; tile += nblocks) {
        const uint32_t a1 = tbase + (buf ? TMEM_A1_1 : TMEM_A1_0);

        // ---- MMA1: D = A1 @ W1  (K=272 -> 17 steps of 16) ----
        if (wid == 0) {
            TC_FENCE_AFTER();
            if (elect_one()) {
                #pragma unroll 1
                for (int s = 0; s < 17; ++s)
                    TC_MMA_BF16(tbase + TMEM_DD, a1 + s * 8, w1d + koff(s), s > 0);
                TC_COMMIT(mbar);
            }
        }
        // ---- prefetch next tile's gather into the other buffer (overlaps MMA1)
        const int nxt = tile + nblocks;
        if (nxt < NTILES) gather(nxt, buf ^ 1);
        TC_FENCE_BEFORE();

        MBAR_WAIT(mbar, ph); ph ^= 1;
        TC_FENCE_AFTER();

        // ---- E1: D -> bias+silu -> A2 (bf16) ----
        #pragma unroll 1
        for (int ch = 0; ch < 4; ++ch) {
            uint32_t dreg[32], areg[16];
            TC_LD_X32(dreg, tbase + TMEM_DD + ch * 32);
            TC_WAIT_LD();
            #pragma unroll
            for (int m = 0; m < 16; ++m) {
                float v0 = silu_f(__uint_as_float(dreg[2*m])   + s_eb1[ch*32 + 2*m]);
                float v1 = silu_f(__uint_as_float(dreg[2*m+1]) + s_eb1[ch*32 + 2*m+1]);
                areg[m] = pack_bf16x2(v0, v1);
            }
            TC_ST_X16(tbase + TMEM_A2 + ch * 16 + woff, areg);
        }
        TC_WAIT_ST();
        TC_FENCE_BEFORE();
        __syncthreads();

        // ---- MMA2: D = A2 @ W2  (K=128 -> 8 steps), reuses D region ----
        if (wid == 0) {
            TC_FENCE_AFTER();
            if (elect_one()) {
                #pragma unroll 1
                for (int s = 0; s < 8; ++s)
                    TC_MMA_BF16(tbase + TMEM_DD, tbase + TMEM_A2 + s * 8,
                                w2d + koff(s), s > 0);
                TC_COMMIT(mbar);
            }
        }
        MBAR_WAIT(mbar, ph); ph ^= 1;
        TC_FENCE_AFTER();

        // ---- E2: D -> bias+silu -> scatter-add ----
        {
            const int e = tile * TM + tid;
            float* aggp = g_agg + (size_t)g_row[e] * D;
            #pragma unroll 1
            for (int ch = 0; ch < 4; ++ch) {
                uint32_t dreg[32];
                TC_LD_X32(dreg, tbase + TMEM_DD + ch * 32);
                TC_WAIT_LD();
                #pragma unroll
                for (int q = 0; q < 8; ++q) {
                    float v0 = silu_f(__uint_as_float(dreg[q*4+0]) + s_eb2[ch*32+q*4+0]);
                    float v1 = silu_f(__uint_as_float(dreg[q*4+1]) + s_eb2[ch*32+q*4+1]);
                    float v2 = silu_f(__uint_as_float(dreg[q*4+2]) + s_eb2[ch*32+q*4+2]);
                    float v3 = silu_f(__uint_as_float(dreg[q*4+3]) + s_eb2[ch*32+q*4+3]);
                    asm volatile("red.global.add.v4.f32 [%0], {%1,%2,%3,%4};"
                                 :: "l"(aggp + ch * 32 + q * 4),
                                    "f"(v0), "f"(v1), "f"(v2), "f"(v3) : "memory");
                }
            }
        }
        TC_FENCE_BEFORE();
        __syncthreads();
        buf ^= 1;
    }

    __syncthreads();
    if (wid == 0) { TC_RELINQ(); TC_DEALLOC(tbase, 512); }

#else
    // plain-sm_103 fallback (never selected on GB300; driver loads sm_103a cubin)
    const int tid = threadIdx.x;
    for (int tile = blockIdx.x; tile < NTILES; tile += nblocks) {
        const int e = tile * TM + tid;
        const int r = g_row[e], c = g_col[e];
        float a[K1];
        #pragma unroll 4
        for (int j = 0; j < D; ++j) { a[j] = x[(size_t)r * D + j]; a[D + j] = x[(size_t)c * D + j]; }
        #pragma unroll
        for (int j = 0; j < DE; ++j) a[2 * D + j] = ea[(size_t)e * DE + j];
        float h[D];
        for (int n = 0; n < D; ++n) {
            float s = eb1[n];
            for (int k = 0; k < K1; ++k) s = fmaf(a[k], eW1raw[(size_t)k * D + n], s);
            h[n] = silu_f(s);
        }
        for (int n = 0; n < D; ++n) {
            float s = eb2[n];
            for (int k = 0; k < D; ++k) s = fmaf(h[k], eW2raw[(size_t)k * D + n], s);
            atomicAdd(g_agg + (size_t)r * D + n, silu_f(s));
        }
    }
#endif
}

// ---------------- node layer 1: t = silu([x|agg] @ nW1 + nb1) -----------
__global__ __launch_bounds__(256, 1) void k_node1(
    const float* __restrict__ x, const float* __restrict__ W,
    const float* __restrict__ b)
{
    extern __shared__ float sm[];
    float* Ws = sm;
    float* As = sm + K3DIM * D;
    __shared__ float bs[D];

    const int tid = threadIdx.x;
    const int tx = tid & 31;
    const int ty = tid >> 5;
    {
        const float4* src = (const float4*)W;
        float4* dst = (float4*)Ws;
        for (int i = tid; i < K3DIM * D / 4; i += 256) dst[i] = src[i];
        if (tid < D) bs[tid] = b[tid];
    }
    __syncthreads();

    const int n0 = blockIdx.x * TE;
    for (int idx = tid; idx < TE * D; idx += 256) {
        const int nl = idx >> 7, k = idx & 127;
        const int n = n0 + nl;
        float xv = 0.f, av = 0.f;
        if (n < N_NODES) {
            xv = x[(size_t)n * D + k];
            av = g_agg[(size_t)n * D + k];
        }
        As[nl * K3DIM + k] = xv;
        As[nl * K3DIM + D + k] = av;
    }
    __syncthreads();

    float4 acc[8];
    #pragma unroll
    for (int m = 0; m < 8; ++m) acc[m] = make_float4(0.f, 0.f, 0.f, 0.f);
    const float* Ar = As + (ty * 8) * K3DIM;
    #pragma unroll 4
    for (int k = 0; k < K3DIM; ++k) {
        float4 bv = *(const float4*)(Ws + k * D + 4 * tx);
        #pragma unroll
        for (int m = 0; m < 8; ++m) {
            float a = Ar[m * K3DIM + k];
            acc[m].x = fmaf(a, bv.x, acc[m].x);
            acc[m].y = fmaf(a, bv.y, acc[m].y);
            acc[m].z = fmaf(a, bv.z, acc[m].z);
            acc[m].w = fmaf(a, bv.w, acc[m].w);
        }
    }
    float4 bb = *(const float4*)(bs + 4 * tx);
    #pragma unroll
    for (int m = 0; m < 8; ++m) {
        const int n = n0 + ty * 8 + m;
        if (n < N_NODES) {
            float4 v = acc[m];
            v.x = silu_f(v.x + bb.x);
            v.y = silu_f(v.y + bb.y);
            v.z = silu_f(v.z + bb.z);
            v.w = silu_f(v.w + bb.w);
            *(float4*)(g_t + (size_t)n * D + 4 * tx) = v;
        }
    }
}

// ---------------- node layer 2 + residual --------------------------------
__global__ __launch_bounds__(256, 2) void k_node2(
    const float* __restrict__ x, const float* __restrict__ W,
    const float* __restrict__ b, float* __restrict__ out)
{
    extern __shared__ float sm[];
    float* Ws = sm;
    float* Ts = sm + D * D;
    __shared__ float bs[D];

    const int tid = threadIdx.x;
    const int tx = tid & 31;
    const int ty = tid >> 5;
    {
        const float4* src = (const float4*)W;
        float4* dst = (float4*)Ws;
        for (int i = tid; i < D * D / 4; i += 256) dst[i] = src[i];
        if (tid < D) bs[tid] = b[tid];
    }
    __syncthreads();

    const int n0 = blockIdx.x * TE;
    for (int idx = tid; idx < TE * D; idx += 256) {
        const int nl = idx >> 7, k = idx & 127;
        const int n = n0 + nl;
        Ts[idx] = (n < N_NODES) ? g_t[(size_t)n * D + k] : 0.f;
    }
    __syncthreads();

    float4 acc[8];
    #pragma unroll
    for (int m = 0; m < 8; ++m) acc[m] = make_float4(0.f, 0.f, 0.f, 0.f);
    const float* Ar = Ts + (ty * 8) * D;
    #pragma unroll 4
    for (int k = 0; k < D; ++k) {
        float4 bv = *(const float4*)(Ws + k * D + 4 * tx);
        #pragma unroll
        for (int m = 0; m < 8; ++m) {
            float a = Ar[m * D + k];
            acc[m].x = fmaf(a, bv.x, acc[m].x);
            acc[m].y = fmaf(a, bv.y, acc[m].y);
            acc[m].z = fmaf(a, bv.z, acc[m].z);
            acc[m].w = fmaf(a, bv.w, acc[m].w);
        }
    }
    float4 bb = *(const float4*)(bs + 4 * tx);
    #pragma unroll
    for (int m = 0; m < 8; ++m) {
        const int n = n0 + ty * 8 + m;
        if (n < N_NODES) {
            float4 xv = *(const float4*)(x + (size_t)n * D + 4 * tx);
            float4 v = acc[m];
            v.x += bb.x + xv.x;
            v.y += bb.y + xv.y;
            v.z += bb.z + xv.z;
            v.w += bb.w + xv.w;
            *(float4*)(out + (size_t)n * D + 4 * tx) = v;
        }
    }
}

// ---------------- launch --------------------------------------------------
extern "C" void kernel_launch(void* const* d_in, const int* in_sizes, int n_in,
                              void* d_out, int out_size)
{
    const float* x   = (const float*)d_in[0];
    const void*  ei  = d_in[1];
    const float* ea  = (const float*)d_in[2];
    const float* eW1 = (const float*)d_in[3];
    const float* eb1 = (const float*)d_in[4];
    const float* eW2 = (const float*)d_in[5];
    const float* eb2 = (const float*)d_in[6];
    const float* nW1 = (const float*)d_in[7];
    const float* nb1 = (const float*)d_in[8];
    const float* nW2 = (const float*)d_in[9];
    const float* nb2 = (const float*)d_in[10];
    float* out = (float*)d_out;

    int sms = 148;
    cudaDeviceGetAttribute(&sms, cudaDevAttrMultiProcessorCount, 0);

    const int s_edge = 1024 + W1B_BYTES + W2B_BYTES;                 // 115,712
    const int s_n1 = (K3DIM * D + TE * K3DIM) * (int)sizeof(float);  // 196,608
    const int s_n2 = (D * D + TE * D) * (int)sizeof(float);          //  98,304

    cudaFuncSetAttribute(k_edge_fused, cudaFuncAttributeMaxDynamicSharedMemorySize, s_edge);
    cudaFuncSetAttribute(k_node1, cudaFuncAttributeMaxDynamicSharedMemorySize, s_n1);
    cudaFuncSetAttribute(k_node2, cudaFuncAttributeMaxDynamicSharedMemorySize, s_n2);

    const int ntiles = (N_NODES + TE - 1) / TE;
    const int prep_elems = 128 * K1PAD + 128 * 128;
    const size_t cz = (size_t)N_NODES * D;   // 6.4M >= N_EDGES

    // launch order keeps k_edge_fused at index 3 (ncu -s 5 capture slot)
    k_detect<<<1, 1>>>((const int*)ei);
    k_convert_zero<<<(int)((cz + 255) / 256), 256>>>(ei);
    k_prep<<<(prep_elems + 255) / 256, 256>>>(eW1, eW2);
    k_edge_fused<<<sms, 128, s_edge>>>(x, ea, eb1, eb2, eW1, eW2, sms);
    k_node1<<<ntiles, 256, s_n1>>>(x, nW1, nb1);
    k_node2<<<ntiles, 256, s_n2>>>(x, nW2, nb2, out);
}

// round 6
// speedup vs baseline: 2.3440x; 1.1535x over previous
#include <cuda_runtime.h>
#include <cuda_bf16.h>
#include <cstdint>

#define N_NODES 50000
#define N_EDGES 800000
#define D 128
#define DE 16
#define K1 272            // 2*D + DE
#define K1PAD 320         // 5 SW128 atom cols of 64 bf16
#define TM 128            // edges per tile
#define NTILES (N_EDGES / TM)   // 6250
#define K3DIM 256
#define TE 64

#define W1B_BYTES (128 * K1PAD * 2)   // 81920
#define W2B_BYTES (128 * 128 * 2)     // 32768
#define A1B_BYTES (128 * K1PAD * 2)   // 81920

// TMEM columns
#define TMEM_D1 0       // 128 cols fp32
#define TMEM_D2 128     // 128 cols fp32
#define TMEM_A2 256     // 64 cols bf16

#define IDESC_BF16 0x8200490u   // F32 acc | aBF16 | bBF16 | N=128 | M=128

// ---------------- scratch -----------------------------------------------
__device__ int      g_is64;
__device__ int      g_row[N_EDGES];
__device__ int      g_col[N_EDGES];
__device__ float    g_agg[(size_t)N_NODES * D];
__device__ float    g_t[(size_t)N_NODES * D];
__device__ uint16_t g_W1B[W1B_BYTES / 2];
__device__ uint16_t g_W2B[W2B_BYTES / 2];

__device__ __forceinline__ float silu_f(float v) {
    return v / (1.0f + __expf(-v));
}
__device__ __forceinline__ uint32_t smem_u32(const void* p) {
    uint32_t a;
    asm("{ .reg .u64 t; cvta.to.shared.u64 t, %1; cvt.u32.u64 %0, t; }"
        : "=r"(a) : "l"(p));
    return a;
}
__device__ __forceinline__ uint32_t pack_bf16x2(float lo, float hi) {
    uint32_t d;
    asm("cvt.rn.bf16x2.f32 %0, %1, %2;" : "=r"(d) : "f"(hi), "f"(lo));
    return d;
}
__device__ __forceinline__ uint16_t bf16_bits(float v) {
    __nv_bfloat16 b = __float2bfloat16(v);
    return *reinterpret_cast<uint16_t*>(&b);
}
__device__ __forceinline__ void sts8(uint32_t addr, uint32_t a, uint32_t b) {
    asm volatile("st.shared.v2.b32 [%0], {%1, %2};" :: "r"(addr), "r"(a), "r"(b) : "memory");
}
// A1/W blocked-atom byte offset (row in [0,128), k in [0,K1PAD))
__device__ __forceinline__ uint32_t abyte(int row, int k) {
    return (uint32_t)((((row >> 3) + ((k >> 6) << 4)) << 10) | ((row & 7) << 7) | ((k & 63) << 1));
}
__device__ __forceinline__ uint32_t swz(uint32_t b) {
    return b ^ ((b >> 3) & 0x70);
}

#if defined(__CUDA_ARCH__) && defined(__CUDA_ARCH_FEAT_SM103_ALL)

__device__ __forceinline__ uint32_t elect_one() {
    uint32_t pred;
    asm volatile("{\n\t.reg .pred p;\n\telect.sync _|p, 0xFFFFFFFF;\n\t"
                 "selp.b32 %0, 1, 0, p;\n\t}" : "=r"(pred));
    return pred;
}

#define TC_ALLOC(smemaddr, n) \
    asm volatile("tcgen05.alloc.cta_group::1.sync.aligned.shared::cta.b32 [%0], %1;" \
                 :: "r"(smemaddr), "r"((uint32_t)(n)) : "memory")
#define TC_RELINQ() \
    asm volatile("tcgen05.relinquish_alloc_permit.cta_group::1.sync.aligned;")
#define TC_DEALLOC(tmem, n) \
    asm volatile("tcgen05.dealloc.cta_group::1.sync.aligned.b32 %0, %1;" \
                 :: "r"(tmem), "r"((uint32_t)(n)))
#define TC_WAIT_ST() asm volatile("tcgen05.wait::st.sync.aligned;" ::: "memory")
#define TC_WAIT_LD() asm volatile("tcgen05.wait::ld.sync.aligned;" ::: "memory")
#define TC_FENCE_BEFORE() asm volatile("tcgen05.fence::before_thread_sync;" ::: "memory")
#define TC_FENCE_AFTER()  asm volatile("tcgen05.fence::after_thread_sync;" ::: "memory")
#define TC_COMMIT(mbar) \
    asm volatile("tcgen05.commit.cta_group::1.mbarrier::arrive::one.shared::cluster.b64 [%0];" \
                 :: "r"(mbar) : "memory")
#define MBAR_INIT(mbar, cnt) \
    asm volatile("mbarrier.init.shared.b64 [%0], %1;" :: "r"(mbar), "r"((uint32_t)(cnt)) : "memory")
#define FENCE_PROXY_ASYNC() \
    asm volatile("fence.proxy.async.shared::cta;" ::: "memory")
#define NAMED_BAR(id, n) \
    asm volatile("bar.sync %0, %1;" :: "r"(id), "r"(n) : "memory")

#define MBAR_WAIT(mbar, ph) do {                                             \
    uint32_t _m = (mbar), _p = (uint32_t)(ph), _d;                           \
    asm volatile("{\n\t.reg .pred p;\n\t"                                    \
        "mbarrier.try_wait.parity.acquire.cta.shared::cta.b64 p, [%1], %2;\n\t" \
        "selp.b32 %0, 1, 0, p;\n\t}" : "=r"(_d) : "r"(_m), "r"(_p) : "memory"); \
    if (!_d) {                                                               \
        asm volatile("{\n\t.reg .pred P1;\n\t"                               \
            "WL_%=:\n\t"                                                     \
            "mbarrier.try_wait.parity.acquire.cta.shared::cta.b64 P1, [%0], %1, 0x989680;\n\t" \
            "@P1 bra.uni WD_%=;\n\t"                                         \
            "bra.uni WL_%=;\n\t"                                             \
            "WD_%=:\n\t}" :: "r"(_m), "r"(_p) : "memory");                   \
    }                                                                        \
} while (0)

// SS-form: both operands SMEM descriptors
#define TC_MMA_SS(dtm, adesc, bdesc, en) do {                                \
    uint32_t _e = (en) ? 1u : 0u;                                            \
    asm volatile("{\n\t.reg .pred p;\n\t"                                    \
        "setp.ne.u32 p, %5, 0;\n\t"                                          \
        "tcgen05.mma.cta_group::1.kind::f16 [%0], %1, %2, %3, {%4, %4, %4, %4}, p;\n\t" \
        "}" :: "r"(dtm), "l"(adesc), "l"(bdesc), "r"(IDESC_BF16),            \
               "r"(0u), "r"(_e) : "memory");                                 \
} while (0)

// TS-form: A in TMEM
#define TC_MMA_TS(dtm, atm, bdesc, en) do {                                  \
    uint32_t _e = (en) ? 1u : 0u;                                            \
    asm volatile("{\n\t.reg .pred p;\n\t"                                    \
        "setp.ne.u32 p, %5, 0;\n\t"                                          \
        "tcgen05.mma.cta_group::1.kind::f16 [%0], [%1], %2, %3, {%4, %4, %4, %4}, p;\n\t" \
        "}" :: "r"(dtm), "r"(atm), "l"(bdesc), "r"(IDESC_BF16),              \
               "r"(0u), "r"(_e) : "memory");                                 \
} while (0)

#define TC_ST_X16(tmem_addr, r)                                              \
    asm volatile("tcgen05.st.sync.aligned.32x32b.x16.b32 [%0], "             \
        "{%1, %2, %3, %4, %5, %6, %7, %8, "                                  \
        " %9, %10, %11, %12, %13, %14, %15, %16};"                           \
        :: "r"(tmem_addr),                                                   \
           "r"((r)[0]),  "r"((r)[1]),  "r"((r)[2]),  "r"((r)[3]),            \
           "r"((r)[4]),  "r"((r)[5]),  "r"((r)[6]),  "r"((r)[7]),            \
           "r"((r)[8]),  "r"((r)[9]),  "r"((r)[10]), "r"((r)[11]),           \
           "r"((r)[12]), "r"((r)[13]), "r"((r)[14]), "r"((r)[15])            \
        : "memory")

#define TC_LD_X32(r, tmem_addr)                                              \
    asm volatile("tcgen05.ld.sync.aligned.32x32b.x32.b32 "                   \
        "{%0, %1, %2, %3, %4, %5, %6, %7, "                                  \
        " %8, %9, %10, %11, %12, %13, %14, %15, "                            \
        " %16, %17, %18, %19, %20, %21, %22, %23, "                          \
        " %24, %25, %26, %27, %28, %29, %30, %31}, [%32];"                   \
        : "=r"((r)[0]),  "=r"((r)[1]),  "=r"((r)[2]),  "=r"((r)[3]),         \
          "=r"((r)[4]),  "=r"((r)[5]),  "=r"((r)[6]),  "=r"((r)[7]),         \
          "=r"((r)[8]),  "=r"((r)[9]),  "=r"((r)[10]), "=r"((r)[11]),        \
          "=r"((r)[12]), "=r"((r)[13]), "=r"((r)[14]), "=r"((r)[15]),        \
          "=r"((r)[16]), "=r"((r)[17]), "=r"((r)[18]), "=r"((r)[19]),        \
          "=r"((r)[20]), "=r"((r)[21]), "=r"((r)[22]), "=r"((r)[23]),        \
          "=r"((r)[24]), "=r"((r)[25]), "=r"((r)[26]), "=r"((r)[27]),        \
          "=r"((r)[28]), "=r"((r)[29]), "=r"((r)[30]), "=r"((r)[31])         \
        : "r"(tmem_addr))

static constexpr unsigned long long SMEM_DESC_BASE =
    (2ull << 61) | (1ull << 46) | (64ull << 32) | (1ull << 16);
__device__ __forceinline__ uint64_t mk_desc(uint32_t addr) {
    return SMEM_DESC_BASE | ((uint64_t)(addr >> 4) & 0x3FFF);
}
// K-step s = 16 bf16 = 32B; atom col = s>>2; atom-col stride 16*1024B = 1024 units
__device__ __forceinline__ uint64_t koff(int s) {
    return (uint64_t)((s >> 2) * 1024 + (s & 3) * 2);
}

#endif // sm_103a device helpers

// ---------------- small kernels ------------------------------------------
__global__ void k_detect(const int* ei32) {
    if (blockIdx.x == 0 && threadIdx.x == 0) {
        int is64 = 1;
        #pragma unroll 1
        for (int i = 0; i < 64; ++i)
            if (ei32[2 * i + 1] != 0) { is64 = 0; break; }
        g_is64 = is64;
    }
}
__global__ void k_convert_zero(const void* ei) {
    size_t i = (size_t)blockIdx.x * blockDim.x + threadIdx.x;
    if (i < N_EDGES) {
        if (g_is64) {
            const long long* p = (const long long*)ei;
            g_row[i] = (int)p[i];
            g_col[i] = (int)p[(size_t)N_EDGES + i];
        } else {
            const int* p = (const int*)ei;
            g_row[i] = p[i];
            g_col[i] = p[N_EDGES + i];
        }
    }
    if (i < (size_t)N_NODES * D) g_agg[i] = 0.0f;
}
__global__ void k_prep(const float* __restrict__ W1, const float* __restrict__ W2) {
    int i = blockIdx.x * blockDim.x + threadIdx.x;
    if (i < 128 * K1PAD) {
        int n = i / K1PAD, k = i % K1PAD;
        float v = (k < K1) ? W1[(size_t)k * 128 + n] : 0.0f;
        g_W1B[swz(abyte(n, k)) >> 1] = bf16_bits(v);
    } else {
        i -= 128 * K1PAD;
        if (i >= 128 * 128) return;
        int n = i / 128, k = i % 128;
        g_W2B[swz(abyte(n, k)) >> 1] = bf16_bits(W2[(size_t)k * 128 + n]);
    }
}

// ---------------- fused edge kernel: SS MMA1 + warp-specialized pipeline --
__global__ __launch_bounds__(256, 1) void k_edge_fused(
    const float* __restrict__ x, const float* __restrict__ ea,
    const float* __restrict__ eb1, const float* __restrict__ eb2,
    const float* __restrict__ eW1raw, const float* __restrict__ eW2raw,
    int nblocks)
{
#if defined(__CUDA_ARCH__) && defined(__CUDA_ARCH_FEAT_SM103_ALL)
    extern __shared__ uint32_t dsm[];
    __shared__ float s_eb1[D], s_eb2[D];
    __shared__ uint32_t s_tmem[1];
    __shared__ __align__(8) unsigned long long s_mbar1, s_mbar2;

    const int tid = threadIdx.x;
    const int wid = tid >> 5;
    const int lane = tid & 31;

    const uint32_t dyn_base = smem_u32(dsm);
    const uint32_t ws1 = (dyn_base + 1023u) & ~1023u;   // W1  (80KB)
    const uint32_t ws2 = ws1 + W1B_BYTES;               // W2  (32KB)
    const uint32_t wsA = ws2 + W2B_BYTES;               // A1  (80KB)
    uint32_t* w1p = dsm + ((ws1 - dyn_base) >> 2);

    {   // stage pre-swizzled weights + biases; zero A1 K-pad region [272,320)
        uint4* dst = (uint4*)w1p; const uint4* src = (const uint4*)g_W1B;
        for (int i = tid; i < (W1B_BYTES + W2B_BYTES) / 16; i += 256) dst[i] = src[i];
        if (tid < D) { s_eb1[tid] = eb1[tid]; s_eb2[tid] = eb2[tid]; }
        for (int i = tid; i < 128 * 12; i += 256) {
            int row = i / 12, j = i % 12;
            sts8(wsA + swz(abyte(row, 272 + j * 4)), 0u, 0u);
        }
    }
    if (wid == 0) TC_ALLOC(smem_u32(s_tmem), 512);
    if (tid == 0) { MBAR_INIT(smem_u32(&s_mbar1), 1); MBAR_INIT(smem_u32(&s_mbar2), 1); }
    __syncthreads();
    const uint32_t tbase = s_tmem[0];
    const uint32_t mbar1 = smem_u32(&s_mbar1);
    const uint32_t mbar2 = smem_u32(&s_mbar2);
    const uint64_t a1d = mk_desc(wsA);
    const uint64_t w1d = mk_desc(ws1);
    const uint64_t w2d = mk_desc(ws2);

    // warp-cooperative coalesced gather: warp gw fills A1 rows gw*32..gw*32+31
    auto gather = [&](int tile) {
        const int gw = wid;
        const int e0 = tile * TM + gw * 32;
        const int myr = g_row[e0 + lane];
        const int myc = g_col[e0 + lane];
        #pragma unroll 4
        for (int i = 0; i < 32; ++i) {
            const int el = gw * 32 + i;
            const int r = __shfl_sync(0xffffffffu, myr, i);
            const int c = __shfl_sync(0xffffffffu, myc, i);
            float4 v = *(const float4*)(x + (size_t)r * D + lane * 4);
            sts8(wsA + swz(abyte(el, lane * 4)),
                 pack_bf16x2(v.x, v.y), pack_bf16x2(v.z, v.w));
            v = *(const float4*)(x + (size_t)c * D + lane * 4);
            sts8(wsA + swz(abyte(el, 128 + lane * 4)),
                 pack_bf16x2(v.x, v.y), pack_bf16x2(v.z, v.w));
        }
        #pragma unroll
        for (int i = 0; i < 4; ++i) {
            const int el = gw * 32 + i * 8 + (lane >> 2);
            const int e = tile * TM + el;
            float4 v = *(const float4*)(ea + (size_t)e * DE + (lane & 3) * 4);
            sts8(wsA + swz(abyte(el, 256 + (lane & 3) * 4)),
                 pack_bf16x2(v.x, v.y), pack_bf16x2(v.z, v.w));
        }
    };

    // prologue: gather first tile
    if (wid < 4 && blockIdx.x < NTILES) { gather(blockIdx.x); FENCE_PROXY_ASYNC(); }

    int ph1 = 0, ph2 = 0;
    for (int tile = blockIdx.x; tile < NTILES; tile += nblocks) {
        __syncthreads();   // A1(tile) ready; D regions free

        // ---- MMA1 (SS): D1 = A1 @ W1, K=272 -> 17 steps ----
        if (wid == 4) {
            TC_FENCE_AFTER();
            if (elect_one()) {
                #pragma unroll 1
                for (int s = 0; s < 17; ++s)
                    TC_MMA_SS(tbase + TMEM_D1, a1d + koff(s), w1d + koff(s), s > 0);
                TC_COMMIT(mbar1);
            }
        }

        if (wid < 4) {
            // ---- G-warps: wait A1 consumed, then gather next tile ----
            MBAR_WAIT(mbar1, ph1);
            const int nxt = tile + nblocks;
            if (nxt < NTILES) { gather(nxt); FENCE_PROXY_ASYNC(); }
        } else {
            const int w4 = wid & 3;
            MBAR_WAIT(mbar1, ph1);
            TC_FENCE_AFTER();

            // ---- E1: D1 -> bias+silu -> A2 (TMEM bf16) ----
            #pragma unroll 1
            for (int ch = 0; ch < 4; ++ch) {
                uint32_t dreg[32], areg[16];
                TC_LD_X32(dreg, tbase + TMEM_D1 + ch * 32);
                TC_WAIT_LD();
                #pragma unroll
                for (int m = 0; m < 16; ++m) {
                    float v0 = silu_f(__uint_as_float(dreg[2*m])   + s_eb1[ch*32 + 2*m]);
                    float v1 = silu_f(__uint_as_float(dreg[2*m+1]) + s_eb1[ch*32 + 2*m+1]);
                    areg[m] = pack_bf16x2(v0, v1);
                }
                TC_ST_X16(tbase + TMEM_A2 + ch * 16 + ((uint32_t)w4 << 21), areg);
            }
            TC_WAIT_ST();
            TC_FENCE_BEFORE();
            NAMED_BAR(1, 128);

            // ---- MMA2 (TS): D2 = A2 @ W2, K=128 -> 8 steps ----
            if (wid == 4) {
                TC_FENCE_AFTER();
                if (elect_one()) {
                    #pragma unroll 1
                    for (int s = 0; s < 8; ++s)
                        TC_MMA_TS(tbase + TMEM_D2, tbase + TMEM_A2 + s * 8,
                                  w2d + koff(s), s > 0);
                    TC_COMMIT(mbar2);
                }
            }
            MBAR_WAIT(mbar2, ph2); ph2 ^= 1;
            TC_FENCE_AFTER();

            // ---- E2: D2 -> bias+silu -> scatter-add ----
            {
                const int e = tile * TM + w4 * 32 + lane;
                float* aggp = g_agg + (size_t)g_row[e] * D;
                #pragma unroll 1
                for (int ch = 0; ch < 4; ++ch) {
                    uint32_t dreg[32];
                    TC_LD_X32(dreg, tbase + TMEM_D2 + ch * 32);
                    TC_WAIT_LD();
                    #pragma unroll
                    for (int q = 0; q < 8; ++q) {
                        float v0 = silu_f(__uint_as_float(dreg[q*4+0]) + s_eb2[ch*32+q*4+0]);
                        float v1 = silu_f(__uint_as_float(dreg[q*4+1]) + s_eb2[ch*32+q*4+1]);
                        float v2 = silu_f(__uint_as_float(dreg[q*4+2]) + s_eb2[ch*32+q*4+2]);
                        float v3 = silu_f(__uint_as_float(dreg[q*4+3]) + s_eb2[ch*32+q*4+3]);
                        asm volatile("red.global.add.v4.f32 [%0], {%1,%2,%3,%4};"
                                     :: "l"(aggp + ch * 32 + q * 4),
                                        "f"(v0), "f"(v1), "f"(v2), "f"(v3) : "memory");
                    }
                }
            }
            TC_FENCE_BEFORE();
        }
        ph1 ^= 1;
    }

    __syncthreads();
    if (wid == 0) { TC_RELINQ(); TC_DEALLOC(tbase, 512); }

#else
    // plain-sm_103 fallback (never selected on GB300; driver loads sm_103a cubin)
    const int tid = threadIdx.x;
    if (tid >= TM) return;
    for (int tile = blockIdx.x; tile < NTILES; tile += nblocks) {
        const int e = tile * TM + tid;
        const int r = g_row[e], c = g_col[e];
        float a[K1];
        #pragma unroll 4
        for (int j = 0; j < D; ++j) { a[j] = x[(size_t)r * D + j]; a[D + j] = x[(size_t)c * D + j]; }
        #pragma unroll
        for (int j = 0; j < DE; ++j) a[2 * D + j] = ea[(size_t)e * DE + j];
        float h[D];
        for (int n = 0; n < D; ++n) {
            float s = eb1[n];
            for (int k = 0; k < K1; ++k) s = fmaf(a[k], eW1raw[(size_t)k * D + n], s);
            h[n] = silu_f(s);
        }
        for (int n = 0; n < D; ++n) {
            float s = eb2[n];
            for (int k = 0; k < D; ++k) s = fmaf(h[k], eW2raw[(size_t)k * D + n], s);
            atomicAdd(g_agg + (size_t)r * D + n, silu_f(s));
        }
    }
#endif
}

// ---------------- node layer 1: t = silu([x|agg] @ nW1 + nb1) -----------
__global__ __launch_bounds__(256, 1) void k_node1(
    const float* __restrict__ x, const float* __restrict__ W,
    const float* __restrict__ b)
{
    extern __shared__ float sm[];
    float* Ws = sm;
    float* As = sm + K3DIM * D;
    __shared__ float bs[D];

    const int tid = threadIdx.x;
    const int tx = tid & 31;
    const int ty = tid >> 5;
    {
        const float4* src = (const float4*)W;
        float4* dst = (float4*)Ws;
        for (int i = tid; i < K3DIM * D / 4; i += 256) dst[i] = src[i];
        if (tid < D) bs[tid] = b[tid];
    }
    __syncthreads();

    const int n0 = blockIdx.x * TE;
    for (int idx = tid; idx < TE * D; idx += 256) {
        const int nl = idx >> 7, k = idx & 127;
        const int n = n0 + nl;
        float xv = 0.f, av = 0.f;
        if (n < N_NODES) {
            xv = x[(size_t)n * D + k];
            av = g_agg[(size_t)n * D + k];
        }
        As[nl * K3DIM + k] = xv;
        As[nl * K3DIM + D + k] = av;
    }
    __syncthreads();

    float4 acc[8];
    #pragma unroll
    for (int m = 0; m < 8; ++m) acc[m] = make_float4(0.f, 0.f, 0.f, 0.f);
    const float* Ar = As + (ty * 8) * K3DIM;
    #pragma unroll 4
    for (int k = 0; k < K3DIM; ++k) {
        float4 bv = *(const float4*)(Ws + k * D + 4 * tx);
        #pragma unroll
        for (int m = 0; m < 8; ++m) {
            float a = Ar[m * K3DIM + k];
            acc[m].x = fmaf(a, bv.x, acc[m].x);
            acc[m].y = fmaf(a, bv.y, acc[m].y);
            acc[m].z = fmaf(a, bv.z, acc[m].z);
            acc[m].w = fmaf(a, bv.w, acc[m].w);
        }
    }
    float4 bb = *(const float4*)(bs + 4 * tx);
    #pragma unroll
    for (int m = 0; m < 8; ++m) {
        const int n = n0 + ty * 8 + m;
        if (n < N_NODES) {
            float4 v = acc[m];
            v.x = silu_f(v.x + bb.x);
            v.y = silu_f(v.y + bb.y);
            v.z = silu_f(v.z + bb.z);
            v.w = silu_f(v.w + bb.w);
            *(float4*)(g_t + (size_t)n * D + 4 * tx) = v;
        }
    }
}

// ---------------- node layer 2 + residual --------------------------------
__global__ __launch_bounds__(256, 2) void k_node2(
    const float* __restrict__ x, const float* __restrict__ W,
    const float* __restrict__ b, float* __restrict__ out)
{
    extern __shared__ float sm[];
    float* Ws = sm;
    float* Ts = sm + D * D;
    __shared__ float bs[D];

    const int tid = threadIdx.x;
    const int tx = tid & 31;
    const int ty = tid >> 5;
    {
        const float4* src = (const float4*)W;
        float4* dst = (float4*)Ws;
        for (int i = tid; i < D * D / 4; i += 256) dst[i] = src[i];
        if (tid < D) bs[tid] = b[tid];
    }
    __syncthreads();

    const int n0 = blockIdx.x * TE;
    for (int idx = tid; idx < TE * D; idx += 256) {
        const int nl = idx >> 7, k = idx & 127;
        const int n = n0 + nl;
        Ts[idx] = (n < N_NODES) ? g_t[(size_t)n * D + k] : 0.f;
    }
    __syncthreads();

    float4 acc[8];
    #pragma unroll
    for (int m = 0; m < 8; ++m) acc[m] = make_float4(0.f, 0.f, 0.f, 0.f);
    const float* Ar = Ts + (ty * 8) * D;
    #pragma unroll 4
    for (int k = 0; k < D; ++k) {
        float4 bv = *(const float4*)(Ws + k * D + 4 * tx);
        #pragma unroll
        for (int m = 0; m < 8; ++m) {
            float a = Ar[m * D + k];
            acc[m].x = fmaf(a, bv.x, acc[m].x);
            acc[m].y = fmaf(a, bv.y, acc[m].y);
            acc[m].z = fmaf(a, bv.z, acc[m].z);
            acc[m].w = fmaf(a, bv.w, acc[m].w);
        }
    }
    float4 bb = *(const float4*)(bs + 4 * tx);
    #pragma unroll
    for (int m = 0; m < 8; ++m) {
        const int n = n0 + ty * 8 + m;
        if (n < N_NODES) {
            float4 xv = *(const float4*)(x + (size_t)n * D + 4 * tx);
            float4 v = acc[m];
            v.x += bb.x + xv.x;
            v.y += bb.y + xv.y;
            v.z += bb.z + xv.z;
            v.w += bb.w + xv.w;
            *(float4*)(out + (size_t)n * D + 4 * tx) = v;
        }
    }
}

// ---------------- launch --------------------------------------------------
extern "C" void kernel_launch(void* const* d_in, const int* in_sizes, int n_in,
                              void* d_out, int out_size)
{
    const float* x   = (const float*)d_in[0];
    const void*  ei  = d_in[1];
    const float* ea  = (const float*)d_in[2];
    const float* eW1 = (const float*)d_in[3];
    const float* eb1 = (const float*)d_in[4];
    const float* eW2 = (const float*)d_in[5];
    const float* eb2 = (const float*)d_in[6];
    const float* nW1 = (const float*)d_in[7];
    const float* nb1 = (const float*)d_in[8];
    const float* nW2 = (const float*)d_in[9];
    const float* nb2 = (const float*)d_in[10];
    float* out = (float*)d_out;

    int sms = 148;
    cudaDeviceGetAttribute(&sms, cudaDevAttrMultiProcessorCount, 0);

    const int s_edge = 1024 + W1B_BYTES + W2B_BYTES + A1B_BYTES;     // 197,632
    const int s_n1 = (K3DIM * D + TE * K3DIM) * (int)sizeof(float);  // 196,608
    const int s_n2 = (D * D + TE * D) * (int)sizeof(float);          //  98,304

    cudaFuncSetAttribute(k_edge_fused, cudaFuncAttributeMaxDynamicSharedMemorySize, s_edge);
    cudaFuncSetAttribute(k_node1, cudaFuncAttributeMaxDynamicSharedMemorySize, s_n1);
    cudaFuncSetAttribute(k_node2, cudaFuncAttributeMaxDynamicSharedMemorySize, s_n2);

    const int ntiles = (N_NODES + TE - 1) / TE;
    const int prep_elems = 128 * K1PAD + 128 * 128;
    const size_t cz = (size_t)N_NODES * D;

    // k_edge_fused stays at launch index 3 (ncu -s 5 capture slot)
    k_detect<<<1, 1>>>((const int*)ei);
    k_convert_zero<<<(int)((cz + 255) / 256), 256>>>(ei);
    k_prep<<<(prep_elems + 255) / 256, 256>>>(eW1, eW2);
    k_edge_fused<<<sms, 256, s_edge>>>(x, ea, eb1, eb2, eW1, eW2, sms);
    k_node1<<<ntiles, 256, s_n1>>>(x, nW1, nb1);
    k_node2<<<ntiles, 256, s_n2>>>(x, nW2, nb2, out);
}

// round 7
// speedup vs baseline: 4.4018x; 1.8779x over previous
#include <cuda_runtime.h>
#include <cuda_bf16.h>
#include <cstdint>

#define N_NODES 50000
#define N_EDGES 800000
#define D 128
#define DE 16
#define K1 272            // 2*D + DE
#define K1PAD 320         // 5 SW128 atom cols of 64 bf16
#define TM 128            // edges per tile
#define NTILES (N_EDGES / TM)   // 6250
#define K3DIM 256
#define TE 64

#define W1B_BYTES (128 * K1PAD * 2)   // 81920
#define W2B_BYTES (128 * 128 * 2)     // 32768
#define A1B_BYTES (128 * K1PAD * 2)   // 81920

// TMEM columns
#define TMEM_D1 0       // 128 cols fp32
#define TMEM_D2 128     // 128 cols fp32
#define TMEM_A2 256     // 64 cols bf16

#define IDESC_BF16 0x8200490u   // F32 acc | aBF16 | bBF16 | N=128 | M=128

// ---------------- scratch -----------------------------------------------
__device__ int      g_is64;
__device__ int      g_row[N_EDGES];
__device__ int      g_col[N_EDGES];
__device__ float    g_agg[(size_t)N_NODES * D];
__device__ float    g_t[(size_t)N_NODES * D];
__device__ uint16_t g_W1B[W1B_BYTES / 2];
__device__ uint16_t g_W2B[W2B_BYTES / 2];

// fast silu: forced MUFU path (ex2.approx + rcp.approx), flag-independent
__device__ __forceinline__ float silu_f(float v) {
    float e, r;
    asm("ex2.approx.ftz.f32 %0, %1;" : "=f"(e) : "f"(-1.4426950408889634f * v));
    asm("rcp.approx.ftz.f32 %0, %1;" : "=f"(r) : "f"(1.0f + e));
    return v * r;
}
__device__ __forceinline__ uint32_t smem_u32(const void* p) {
    uint32_t a;
    asm("{ .reg .u64 t; cvta.to.shared.u64 t, %1; cvt.u32.u64 %0, t; }"
        : "=r"(a) : "l"(p));
    return a;
}
__device__ __forceinline__ uint32_t pack_bf16x2(float lo, float hi) {
    uint32_t d;
    asm("cvt.rn.bf16x2.f32 %0, %1, %2;" : "=r"(d) : "f"(hi), "f"(lo));
    return d;
}
__device__ __forceinline__ uint16_t bf16_bits(float v) {
    __nv_bfloat16 b = __float2bfloat16(v);
    return *reinterpret_cast<uint16_t*>(&b);
}
__device__ __forceinline__ void sts8(uint32_t addr, uint32_t a, uint32_t b) {
    asm volatile("st.shared.v2.b32 [%0], {%1, %2};" :: "r"(addr), "r"(a), "r"(b) : "memory");
}
__device__ __forceinline__ uint32_t abyte(int row, int k) {
    return (uint32_t)((((row >> 3) + ((k >> 6) << 4)) << 10) | ((row & 7) << 7) | ((k & 63) << 1));
}
__device__ __forceinline__ uint32_t swz(uint32_t b) {
    return b ^ ((b >> 3) & 0x70);
}

#if defined(__CUDA_ARCH__) && defined(__CUDA_ARCH_FEAT_SM103_ALL)

__device__ __forceinline__ uint32_t elect_one() {
    uint32_t pred;
    asm volatile("{\n\t.reg .pred p;\n\telect.sync _|p, 0xFFFFFFFF;\n\t"
                 "selp.b32 %0, 1, 0, p;\n\t}" : "=r"(pred));
    return pred;
}

#define TC_ALLOC(smemaddr, n) \
    asm volatile("tcgen05.alloc.cta_group::1.sync.aligned.shared::cta.b32 [%0], %1;" \
                 :: "r"(smemaddr), "r"((uint32_t)(n)) : "memory")
#define TC_RELINQ() \
    asm volatile("tcgen05.relinquish_alloc_permit.cta_group::1.sync.aligned;")
#define TC_DEALLOC(tmem, n) \
    asm volatile("tcgen05.dealloc.cta_group::1.sync.aligned.b32 %0, %1;" \
                 :: "r"(tmem), "r"((uint32_t)(n)))
#define TC_WAIT_ST() asm volatile("tcgen05.wait::st.sync.aligned;" ::: "memory")
#define TC_WAIT_LD() asm volatile("tcgen05.wait::ld.sync.aligned;" ::: "memory")
#define TC_FENCE_BEFORE() asm volatile("tcgen05.fence::before_thread_sync;" ::: "memory")
#define TC_FENCE_AFTER()  asm volatile("tcgen05.fence::after_thread_sync;" ::: "memory")
#define TC_COMMIT(mbar) \
    asm volatile("tcgen05.commit.cta_group::1.mbarrier::arrive::one.shared::cluster.b64 [%0];" \
                 :: "r"(mbar) : "memory")
#define MBAR_INIT(mbar, cnt) \
    asm volatile("mbarrier.init.shared.b64 [%0], %1;" :: "r"(mbar), "r"((uint32_t)(cnt)) : "memory")
#define FENCE_PROXY_ASYNC() \
    asm volatile("fence.proxy.async.shared::cta;" ::: "memory")
#define NAMED_BAR(id, n) \
    asm volatile("bar.sync %0, %1;" :: "r"(id), "r"(n) : "memory")

#define MBAR_WAIT(mbar, ph) do {                                             \
    uint32_t _m = (mbar), _p = (uint32_t)(ph), _d;                           \
    asm volatile("{\n\t.reg .pred p;\n\t"                                    \
        "mbarrier.try_wait.parity.acquire.cta.shared::cta.b64 p, [%1], %2;\n\t" \
        "selp.b32 %0, 1, 0, p;\n\t}" : "=r"(_d) : "r"(_m), "r"(_p) : "memory"); \
    if (!_d) {                                                               \
        asm volatile("{\n\t.reg .pred P1;\n\t"                               \
            "WL_%=:\n\t"                                                     \
            "mbarrier.try_wait.parity.acquire.cta.shared::cta.b64 P1, [%0], %1, 0x989680;\n\t" \
            "@P1 bra.uni WD_%=;\n\t"                                         \
            "bra.uni WL_%=;\n\t"                                             \
            "WD_%=:\n\t}" :: "r"(_m), "r"(_p) : "memory");                   \
    }                                                                        \
} while (0)

#define TC_MMA_SS(dtm, adesc, bdesc, en) do {                                \
    uint32_t _e = (en) ? 1u : 0u;                                            \
    asm volatile("{\n\t.reg .pred p;\n\t"                                    \
        "setp.ne.u32 p, %5, 0;\n\t"                                          \
        "tcgen05.mma.cta_group::1.kind::f16 [%0], %1, %2, %3, {%4, %4, %4, %4}, p;\n\t" \
        "}" :: "r"(dtm), "l"(adesc), "l"(bdesc), "r"(IDESC_BF16),            \
               "r"(0u), "r"(_e) : "memory");                                 \
} while (0)

#define TC_MMA_TS(dtm, atm, bdesc, en) do {                                  \
    uint32_t _e = (en) ? 1u : 0u;                                            \
    asm volatile("{\n\t.reg .pred p;\n\t"                                    \
        "setp.ne.u32 p, %5, 0;\n\t"                                          \
        "tcgen05.mma.cta_group::1.kind::f16 [%0], [%1], %2, %3, {%4, %4, %4, %4}, p;\n\t" \
        "}" :: "r"(dtm), "r"(atm), "l"(bdesc), "r"(IDESC_BF16),              \
               "r"(0u), "r"(_e) : "memory");                                 \
} while (0)

#define TC_ST_X16(tmem_addr, r)                                              \
    asm volatile("tcgen05.st.sync.aligned.32x32b.x16.b32 [%0], "             \
        "{%1, %2, %3, %4, %5, %6, %7, %8, "                                  \
        " %9, %10, %11, %12, %13, %14, %15, %16};"                           \
        :: "r"(tmem_addr),                                                   \
           "r"((r)[0]),  "r"((r)[1]),  "r"((r)[2]),  "r"((r)[3]),            \
           "r"((r)[4]),  "r"((r)[5]),  "r"((r)[6]),  "r"((r)[7]),            \
           "r"((r)[8]),  "r"((r)[9]),  "r"((r)[10]), "r"((r)[11]),           \
           "r"((r)[12]), "r"((r)[13]), "r"((r)[14]), "r"((r)[15])            \
        : "memory")

#define TC_LD_X32(r, tmem_addr)                                              \
    asm volatile("tcgen05.ld.sync.aligned.32x32b.x32.b32 "                   \
        "{%0, %1, %2, %3, %4, %5, %6, %7, "                                  \
        " %8, %9, %10, %11, %12, %13, %14, %15, "                            \
        " %16, %17, %18, %19, %20, %21, %22, %23, "                          \
        " %24, %25, %26, %27, %28, %29, %30, %31}, [%32];"                   \
        : "=r"((r)[0]),  "=r"((r)[1]),  "=r"((r)[2]),  "=r"((r)[3]),         \
          "=r"((r)[4]),  "=r"((r)[5]),  "=r"((r)[6]),  "=r"((r)[7]),         \
          "=r"((r)[8]),  "=r"((r)[9]),  "=r"((r)[10]), "=r"((r)[11]),        \
          "=r"((r)[12]), "=r"((r)[13]), "=r"((r)[14]), "=r"((r)[15]),        \
          "=r"((r)[16]), "=r"((r)[17]), "=r"((r)[18]), "=r"((r)[19]),        \
          "=r"((r)[20]), "=r"((r)[21]), "=r"((r)[22]), "=r"((r)[23]),        \
          "=r"((r)[24]), "=r"((r)[25]), "=r"((r)[26]), "=r"((r)[27]),        \
          "=r"((r)[28]), "=r"((r)[29]), "=r"((r)[30]), "=r"((r)[31])         \
        : "r"(tmem_addr))

static constexpr unsigned long long SMEM_DESC_BASE =
    (2ull << 61) | (1ull << 46) | (64ull << 32) | (1ull << 16);
__device__ __forceinline__ uint64_t mk_desc(uint32_t addr) {
    return SMEM_DESC_BASE | ((uint64_t)(addr >> 4) & 0x3FFF);
}
__device__ __forceinline__ uint64_t koff(int s) {
    return (uint64_t)((s >> 2) * 1024 + (s & 3) * 2);
}

#endif // sm_103a device helpers

// ---------------- small kernels ------------------------------------------
__global__ void k_detect(const int* ei32) {
    if (blockIdx.x == 0 && threadIdx.x == 0) {
        int is64 = 1;
        #pragma unroll 1
        for (int i = 0; i < 64; ++i)
            if (ei32[2 * i + 1] != 0) { is64 = 0; break; }
        g_is64 = is64;
    }
}
__global__ void k_convert_zero(const void* ei) {
    size_t i = (size_t)blockIdx.x * blockDim.x + threadIdx.x;
    if (i < N_EDGES) {
        if (g_is64) {
            const long long* p = (const long long*)ei;
            g_row[i] = (int)p[i];
            g_col[i] = (int)p[(size_t)N_EDGES + i];
        } else {
            const int* p = (const int*)ei;
            g_row[i] = p[i];
            g_col[i] = p[N_EDGES + i];
        }
    }
    if (i < (size_t)N_NODES * D) g_agg[i] = 0.0f;
}
__global__ void k_prep(const float* __restrict__ W1, const float* __restrict__ W2) {
    int i = blockIdx.x * blockDim.x + threadIdx.x;
    if (i < 128 * K1PAD) {
        int n = i / K1PAD, k = i % K1PAD;
        float v = (k < K1) ? W1[(size_t)k * 128 + n] : 0.0f;
        g_W1B[swz(abyte(n, k)) >> 1] = bf16_bits(v);
    } else {
        i -= 128 * K1PAD;
        if (i >= 128 * 128) return;
        int n = i / 128, k = i % 128;
        g_W2B[swz(abyte(n, k)) >> 1] = bf16_bits(W2[(size_t)k * 128 + n]);
    }
}

// ---------------- fused edge kernel ---------------------------------------
__global__ __launch_bounds__(256, 1) void k_edge_fused(
    const float* __restrict__ x, const float* __restrict__ ea,
    const float* __restrict__ eb1, const float* __restrict__ eb2,
    const float* __restrict__ eW1raw, const float* __restrict__ eW2raw,
    int nblocks)
{
#if defined(__CUDA_ARCH__) && defined(__CUDA_ARCH_FEAT_SM103_ALL)
    extern __shared__ uint32_t dsm[];
    __shared__ float s_eb1[D], s_eb2[D];
    __shared__ uint32_t s_tmem[1];
    __shared__ __align__(8) unsigned long long s_mbar1, s_mbar2;

    const int tid = threadIdx.x;
    const int wid = tid >> 5;
    const int lane = tid & 31;

    const uint32_t dyn_base = smem_u32(dsm);
    const uint32_t ws1 = (dyn_base + 1023u) & ~1023u;   // W1  (80KB)
    const uint32_t ws2 = ws1 + W1B_BYTES;               // W2  (32KB)
    const uint32_t wsA = ws2 + W2B_BYTES;               // A1  (80KB)
    uint32_t* w1p = dsm + ((ws1 - dyn_base) >> 2);

    {   // stage pre-swizzled weights + biases; zero A1 K-pad [272,320)
        uint4* dst = (uint4*)w1p; const uint4* src = (const uint4*)g_W1B;
        for (int i = tid; i < (W1B_BYTES + W2B_BYTES) / 16; i += 256) dst[i] = src[i];
        if (tid < D) { s_eb1[tid] = eb1[tid]; s_eb2[tid] = eb2[tid]; }
        for (int i = tid; i < 128 * 12; i += 256) {
            int row = i / 12, j = i % 12;
            sts8(wsA + swz(abyte(row, 272 + j * 4)), 0u, 0u);
        }
    }
    if (wid == 0) TC_ALLOC(smem_u32(s_tmem), 512);
    if (tid == 0) { MBAR_INIT(smem_u32(&s_mbar1), 1); MBAR_INIT(smem_u32(&s_mbar2), 1); }
    __syncthreads();
    const uint32_t tbase = s_tmem[0];
    const uint32_t mbar1 = smem_u32(&s_mbar1);
    const uint32_t mbar2 = smem_u32(&s_mbar2);
    const uint64_t a1d = mk_desc(wsA);
    const uint64_t w1d = mk_desc(ws1);
    const uint64_t w2d = mk_desc(ws2);

    // warp-cooperative coalesced gather (warp gw fills A1 rows gw*32..+31)
    auto gather = [&](int tile) {
        const int gw = wid;
        const int e0 = tile * TM + gw * 32;
        const int myr = g_row[e0 + lane];
        const int myc = g_col[e0 + lane];
        #pragma unroll 8
        for (int i = 0; i < 32; ++i) {
            const int el = gw * 32 + i;
            const int r = __shfl_sync(0xffffffffu, myr, i);
            const int c = __shfl_sync(0xffffffffu, myc, i);
            float4 v = *(const float4*)(x + (size_t)r * D + lane * 4);
            sts8(wsA + swz(abyte(el, lane * 4)),
                 pack_bf16x2(v.x, v.y), pack_bf16x2(v.z, v.w));
            v = *(const float4*)(x + (size_t)c * D + lane * 4);
            sts8(wsA + swz(abyte(el, 128 + lane * 4)),
                 pack_bf16x2(v.x, v.y), pack_bf16x2(v.z, v.w));
        }
        #pragma unroll
        for (int i = 0; i < 4; ++i) {
            const int el = gw * 32 + i * 8 + (lane >> 2);
            const int e = tile * TM + el;
            float4 v = *(const float4*)(ea + (size_t)e * DE + (lane & 3) * 4);
            sts8(wsA + swz(abyte(el, 256 + (lane & 3) * 4)),
                 pack_bf16x2(v.x, v.y), pack_bf16x2(v.z, v.w));
        }
    };

    // E2 half: process 2 chunks [c0, c0+1] of D2 for this warp's subpartition
    auto e2_half = [&](int tile, int c0) {
        const int e = tile * TM + (wid & 3) * 32 + lane;
        float* aggp = g_agg + (size_t)g_row[e] * D;
        uint32_t d0[32], d1[32];
        TC_LD_X32(d0, tbase + TMEM_D2 + c0 * 32);
        TC_LD_X32(d1, tbase + TMEM_D2 + (c0 + 1) * 32);
        TC_WAIT_LD();
        #pragma unroll
        for (int q = 0; q < 8; ++q) {
            float v0 = silu_f(__uint_as_float(d0[q*4+0]) + s_eb2[c0*32+q*4+0]);
            float v1 = silu_f(__uint_as_float(d0[q*4+1]) + s_eb2[c0*32+q*4+1]);
            float v2 = silu_f(__uint_as_float(d0[q*4+2]) + s_eb2[c0*32+q*4+2]);
            float v3 = silu_f(__uint_as_float(d0[q*4+3]) + s_eb2[c0*32+q*4+3]);
            asm volatile("red.global.add.v4.f32 [%0], {%1,%2,%3,%4};"
                         :: "l"(aggp + c0 * 32 + q * 4),
                            "f"(v0), "f"(v1), "f"(v2), "f"(v3) : "memory");
        }
        #pragma unroll
        for (int q = 0; q < 8; ++q) {
            float v0 = silu_f(__uint_as_float(d1[q*4+0]) + s_eb2[(c0+1)*32+q*4+0]);
            float v1 = silu_f(__uint_as_float(d1[q*4+1]) + s_eb2[(c0+1)*32+q*4+1]);
            float v2 = silu_f(__uint_as_float(d1[q*4+2]) + s_eb2[(c0+1)*32+q*4+2]);
            float v3 = silu_f(__uint_as_float(d1[q*4+3]) + s_eb2[(c0+1)*32+q*4+3]);
            asm volatile("red.global.add.v4.f32 [%0], {%1,%2,%3,%4};"
                         :: "l"(aggp + (c0 + 1) * 32 + q * 4),
                            "f"(v0), "f"(v1), "f"(v2), "f"(v3) : "memory");
        }
    };

    if (wid < 4 && blockIdx.x < NTILES) { gather(blockIdx.x); FENCE_PROXY_ASYNC(); }

    int ph1 = 0, ph2 = 0;
    for (int tile = blockIdx.x; tile < NTILES; tile += nblocks) {
        __syncthreads();   // A1(tile) ready; D1/D2 free

        // ---- MMA1 (SS): D1 = A1 @ W1, K=272 -> 17 steps ----
        if (wid == 4) {
            TC_FENCE_AFTER();
            if (elect_one()) {
                #pragma unroll 1
                for (int s = 0; s < 17; ++s)
                    TC_MMA_SS(tbase + TMEM_D1, a1d + koff(s), w1d + koff(s), s > 0);
                TC_COMMIT(mbar1);
            }
        }

        if (wid < 4) {
            // ---- G-warps: wait A1 consumed, prefetch next tile ----
            MBAR_WAIT(mbar1, ph1);
            const int nxt = tile + nblocks;
            if (nxt < NTILES) { gather(nxt); FENCE_PROXY_ASYNC(); }
            // ---- then help with E2 (cols 64..127) ----
            MBAR_WAIT(mbar2, ph2);
            TC_FENCE_AFTER();
            e2_half(tile, 2);
            TC_FENCE_BEFORE();
        } else {
            MBAR_WAIT(mbar1, ph1);
            TC_FENCE_AFTER();

            // ---- E1: D1 -> bias+silu -> A2 (pairs of chunks, 1 wait/pair) ----
            #pragma unroll 1
            for (int half = 0; half < 2; ++half) {
                uint32_t d0[32], d1[32], a0[16], a1r[16];
                const int c0 = half * 2;
                TC_LD_X32(d0, tbase + TMEM_D1 + c0 * 32);
                TC_LD_X32(d1, tbase + TMEM_D1 + (c0 + 1) * 32);
                TC_WAIT_LD();
                #pragma unroll
                for (int m = 0; m < 16; ++m) {
                    float v0 = silu_f(__uint_as_float(d0[2*m])   + s_eb1[c0*32 + 2*m]);
                    float v1 = silu_f(__uint_as_float(d0[2*m+1]) + s_eb1[c0*32 + 2*m+1]);
                    a0[m] = pack_bf16x2(v0, v1);
                }
                #pragma unroll
                for (int m = 0; m < 16; ++m) {
                    float v0 = silu_f(__uint_as_float(d1[2*m])   + s_eb1[(c0+1)*32 + 2*m]);
                    float v1 = silu_f(__uint_as_float(d1[2*m+1]) + s_eb1[(c0+1)*32 + 2*m+1]);
                    a1r[m] = pack_bf16x2(v0, v1);
                }
                const uint32_t wo = (uint32_t)(wid & 3) << 21;
                TC_ST_X16(tbase + TMEM_A2 + c0 * 16 + wo, a0);
                TC_ST_X16(tbase + TMEM_A2 + (c0 + 1) * 16 + wo, a1r);
            }
            TC_WAIT_ST();
            TC_FENCE_BEFORE();
            NAMED_BAR(1, 128);

            // ---- MMA2 (TS): D2 = A2 @ W2, K=128 -> 8 steps ----
            if (wid == 4) {
                TC_FENCE_AFTER();
                if (elect_one()) {
                    #pragma unroll 1
                    for (int s = 0; s < 8; ++s)
                        TC_MMA_TS(tbase + TMEM_D2, tbase + TMEM_A2 + s * 8,
                                  w2d + koff(s), s > 0);
                    TC_COMMIT(mbar2);
                }
            }
            MBAR_WAIT(mbar2, ph2);
            TC_FENCE_AFTER();
            // ---- E2 (cols 0..63) ----
            e2_half(tile, 0);
            TC_FENCE_BEFORE();
        }
        ph1 ^= 1; ph2 ^= 1;
    }

    __syncthreads();
    if (wid == 0) { TC_RELINQ(); TC_DEALLOC(tbase, 512); }

#else
    // plain-sm_103 fallback (never selected on GB300; driver loads sm_103a cubin)
    const int tid = threadIdx.x;
    if (tid >= TM) return;
    for (int tile = blockIdx.x; tile < NTILES; tile += nblocks) {
        const int e = tile * TM + tid;
        const int r = g_row[e], c = g_col[e];
        float a[K1];
        #pragma unroll 4
        for (int j = 0; j < D; ++j) { a[j] = x[(size_t)r * D + j]; a[D + j] = x[(size_t)c * D + j]; }
        #pragma unroll
        for (int j = 0; j < DE; ++j) a[2 * D + j] = ea[(size_t)e * DE + j];
        float h[D];
        for (int n = 0; n < D; ++n) {
            float s = eb1[n];
            for (int k = 0; k < K1; ++k) s = fmaf(a[k], eW1raw[(size_t)k * D + n], s);
            h[n] = silu_f(s);
        }
        for (int n = 0; n < D; ++n) {
            float s = eb2[n];
            for (int k = 0; k < D; ++k) s = fmaf(h[k], eW2raw[(size_t)k * D + n], s);
            atomicAdd(g_agg + (size_t)r * D + n, silu_f(s));
        }
    }
#endif
}

// ---------------- node layer 1 -------------------------------------------
__global__ __launch_bounds__(256, 1) void k_node1(
    const float* __restrict__ x, const float* __restrict__ W,
    const float* __restrict__ b)
{
    extern __shared__ float sm[];
    float* Ws = sm;
    float* As = sm + K3DIM * D;
    __shared__ float bs[D];

    const int tid = threadIdx.x;
    const int tx = tid & 31;
    const int ty = tid >> 5;
    {
        const float4* src = (const float4*)W;
        float4* dst = (float4*)Ws;
        for (int i = tid; i < K3DIM * D / 4; i += 256) dst[i] = src[i];
        if (tid < D) bs[tid] = b[tid];
    }
    __syncthreads();

    const int n0 = blockIdx.x * TE;
    for (int idx = tid; idx < TE * D; idx += 256) {
        const int nl = idx >> 7, k = idx & 127;
        const int n = n0 + nl;
        float xv = 0.f, av = 0.f;
        if (n < N_NODES) {
            xv = x[(size_t)n * D + k];
            av = g_agg[(size_t)n * D + k];
        }
        As[nl * K3DIM + k] = xv;
        As[nl * K3DIM + D + k] = av;
    }
    __syncthreads();

    float4 acc[8];
    #pragma unroll
    for (int m = 0; m < 8; ++m) acc[m] = make_float4(0.f, 0.f, 0.f, 0.f);
    const float* Ar = As + (ty * 8) * K3DIM;
    #pragma unroll 4
    for (int k = 0; k < K3DIM; ++k) {
        float4 bv = *(const float4*)(Ws + k * D + 4 * tx);
        #pragma unroll
        for (int m = 0; m < 8; ++m) {
            float a = Ar[m * K3DIM + k];
            acc[m].x = fmaf(a, bv.x, acc[m].x);
            acc[m].y = fmaf(a, bv.y, acc[m].y);
            acc[m].z = fmaf(a, bv.z, acc[m].z);
            acc[m].w = fmaf(a, bv.w, acc[m].w);
        }
    }
    float4 bb = *(const float4*)(bs + 4 * tx);
    #pragma unroll
    for (int m = 0; m < 8; ++m) {
        const int n = n0 + ty * 8 + m;
        if (n < N_NODES) {
            float4 v = acc[m];
            v.x = silu_f(v.x + bb.x);
            v.y = silu_f(v.y + bb.y);
            v.z = silu_f(v.z + bb.z);
            v.w = silu_f(v.w + bb.w);
            *(float4*)(g_t + (size_t)n * D + 4 * tx) = v;
        }
    }
}

// ---------------- node layer 2 + residual --------------------------------
__global__ __launch_bounds__(256, 2) void k_node2(
    const float* __restrict__ x, const float* __restrict__ W,
    const float* __restrict__ b, float* __restrict__ out)
{
    extern __shared__ float sm[];
    float* Ws = sm;
    float* Ts = sm + D * D;
    __shared__ float bs[D];

    const int tid = threadIdx.x;
    const int tx = tid & 31;
    const int ty = tid >> 5;
    {
        const float4* src = (const float4*)W;
        float4* dst = (float4*)Ws;
        for (int i = tid; i < D * D / 4; i += 256) dst[i] = src[i];
        if (tid < D) bs[tid] = b[tid];
    }
    __syncthreads();

    const int n0 = blockIdx.x * TE;
    for (int idx = tid; idx < TE * D; idx += 256) {
        const int nl = idx >> 7, k = idx & 127;
        const int n = n0 + nl;
        Ts[idx] = (n < N_NODES) ? g_t[(size_t)n * D + k] : 0.f;
    }
    __syncthreads();

    float4 acc[8];
    #pragma unroll
    for (int m = 0; m < 8; ++m) acc[m] = make_float4(0.f, 0.f, 0.f, 0.f);
    const float* Ar = Ts + (ty * 8) * D;
    #pragma unroll 4
    for (int k = 0; k < D; ++k) {
        float4 bv = *(const float4*)(Ws + k * D + 4 * tx);
        #pragma unroll
        for (int m = 0; m < 8; ++m) {
            float a = Ar[m * D + k];
            acc[m].x = fmaf(a, bv.x, acc[m].x);
            acc[m].y = fmaf(a, bv.y, acc[m].y);
            acc[m].z = fmaf(a, bv.z, acc[m].z);
            acc[m].w = fmaf(a, bv.w, acc[m].w);
        }
    }
    float4 bb = *(const float4*)(bs + 4 * tx);
    #pragma unroll
    for (int m = 0; m < 8; ++m) {
        const int n = n0 + ty * 8 + m;
        if (n < N_NODES) {
            float4 xv = *(const float4*)(x + (size_t)n * D + 4 * tx);
            float4 v = acc[m];
            v.x += bb.x + xv.x;
            v.y += bb.y + xv.y;
            v.z += bb.z + xv.z;
            v.w += bb.w + xv.w;
            *(float4*)(out + (size_t)n * D + 4 * tx) = v;
        }
    }
}

// ---------------- launch --------------------------------------------------
extern "C" void kernel_launch(void* const* d_in, const int* in_sizes, int n_in,
                              void* d_out, int out_size)
{
    const float* x   = (const float*)d_in[0];
    const void*  ei  = d_in[1];
    const float* ea  = (const float*)d_in[2];
    const float* eW1 = (const float*)d_in[3];
    const float* eb1 = (const float*)d_in[4];
    const float* eW2 = (const float*)d_in[5];
    const float* eb2 = (const float*)d_in[6];
    const float* nW1 = (const float*)d_in[7];
    const float* nb1 = (const float*)d_in[8];
    const float* nW2 = (const float*)d_in[9];
    const float* nb2 = (const float*)d_in[10];
    float* out = (float*)d_out;

    int sms = 148;
    cudaDeviceGetAttribute(&sms, cudaDevAttrMultiProcessorCount, 0);

    const int s_edge = 1024 + W1B_BYTES + W2B_BYTES + A1B_BYTES;     // 197,632
    const int s_n1 = (K3DIM * D + TE * K3DIM) * (int)sizeof(float);  // 196,608
    const int s_n2 = (D * D + TE * D) * (int)sizeof(float);          //  98,304

    cudaFuncSetAttribute(k_edge_fused, cudaFuncAttributeMaxDynamicSharedMemorySize, s_edge);
    cudaFuncSetAttribute(k_node1, cudaFuncAttributeMaxDynamicSharedMemorySize, s_n1);
    cudaFuncSetAttribute(k_node2, cudaFuncAttributeMaxDynamicSharedMemorySize, s_n2);

    const int ntiles = (N_NODES + TE - 1) / TE;
    const int prep_elems = 128 * K1PAD + 128 * 128;
    const size_t cz = (size_t)N_NODES * D;

    k_detect<<<1, 1>>>((const int*)ei);
    k_convert_zero<<<(int)((cz + 255) / 256), 256>>>(ei);
    k_prep<<<(prep_elems + 255) / 256, 256>>>(eW1, eW2);
    k_edge_fused<<<sms, 256, s_edge>>>(x, ea, eb1, eb2, eW1, eW2, sms);
    k_node1<<<ntiles, 256, s_n1>>>(x, nW1, nb1);
    k_node2<<<ntiles, 256, s_n2>>>(x, nW2, nb2, out);
}

// round 8
// speedup vs baseline: 6.2084x; 1.4104x over previous
#include <cuda_runtime.h>
#include <cuda_bf16.h>
#include <cstdint>

#define N_NODES 50000
#define N_EDGES 800000
#define D 128
#define DE 16
#define K1 272            // 2*D + DE
#define K1PAD 320
#define TM 128
#define NTILES (N_EDGES / TM)           // 6250
#define NNT ((N_NODES + 127) / 128)     // 391

#define W1B_BYTES (128 * K1PAD * 2)   // 81920
#define W2B_BYTES (128 * 128 * 2)     // 32768
#define A1B_BYTES (128 * K1PAD * 2)   // 81920
#define NW1_WORDS (256 * 128)         // tf32 words, 128KB
#define NW2_WORDS (128 * 128)         // 64KB

// edge TMEM
#define TMEM_D1 0
#define TMEM_D2 128
#define TMEM_A2 256
// node TMEM: A1 0..255, D1 256..383, A2 0..127 (reuse), D2 128..255 (reuse)

#define IDESC_BF16 0x8200490u
#define IDESC_TF32 0x8200910u

// ---------------- scratch -----------------------------------------------
__device__ int      g_is64;
__device__ int      g_row[N_EDGES];
__device__ int      g_col[N_EDGES];
__device__ float    g_agg[(size_t)N_NODES * D];
__device__ uint16_t g_W1B[W1B_BYTES / 2];
__device__ uint16_t g_W2B[W2B_BYTES / 2];
__device__ uint32_t g_NW1B[NW1_WORDS];
__device__ uint32_t g_NW2B[NW2_WORDS];

__device__ __forceinline__ float silu_f(float v) {
    float e, r;
    asm("ex2.approx.ftz.f32 %0, %1;" : "=f"(e) : "f"(-1.4426950408889634f * v));
    asm("rcp.approx.ftz.f32 %0, %1;" : "=f"(r) : "f"(1.0f + e));
    return v * r;
}
__device__ __forceinline__ uint32_t smem_u32(const void* p) {
    uint32_t a;
    asm("{ .reg .u64 t; cvta.to.shared.u64 t, %1; cvt.u32.u64 %0, t; }"
        : "=r"(a) : "l"(p));
    return a;
}
__device__ __forceinline__ uint32_t pack_bf16x2(float lo, float hi) {
    uint32_t d;
    asm("cvt.rn.bf16x2.f32 %0, %1, %2;" : "=r"(d) : "f"(hi), "f"(lo));
    return d;
}
__device__ __forceinline__ uint16_t bf16_bits(float v) {
    __nv_bfloat16 b = __float2bfloat16(v);
    return *reinterpret_cast<uint16_t*>(&b);
}
__device__ __forceinline__ uint32_t f2tf32(float f) {
    uint32_t u;
    asm("cvt.rna.tf32.f32 %0, %1;" : "=r"(u) : "f"(f));
    return u;
}
__device__ __forceinline__ void sts8(uint32_t addr, uint32_t a, uint32_t b) {
    asm volatile("st.shared.v2.b32 [%0], {%1, %2};" :: "r"(addr), "r"(a), "r"(b) : "memory");
}
// blocked-atom byte offset for bf16 (2B elems, 64/atom-col)
__device__ __forceinline__ uint32_t abyte(int row, int k) {
    return (uint32_t)((((row >> 3) + ((k >> 6) << 4)) << 10) | ((row & 7) << 7) | ((k & 63) << 1));
}
// blocked-atom byte offset for tf32 (4B elems, 32/atom-col)
__device__ __forceinline__ uint32_t abyte32(int row, int k) {
    return (uint32_t)((((row >> 3) + ((k >> 5) << 4)) << 10) | ((row & 7) << 7) | ((k & 31) << 2));
}
__device__ __forceinline__ uint32_t swz(uint32_t b) {
    return b ^ ((b >> 3) & 0x70);
}

#if defined(__CUDA_ARCH__) && defined(__CUDA_ARCH_FEAT_SM103_ALL)

__device__ __forceinline__ uint32_t elect_one() {
    uint32_t pred;
    asm volatile("{\n\t.reg .pred p;\n\telect.sync _|p, 0xFFFFFFFF;\n\t"
                 "selp.b32 %0, 1, 0, p;\n\t}" : "=r"(pred));
    return pred;
}

#define TC_ALLOC(smemaddr, n) \
    asm volatile("tcgen05.alloc.cta_group::1.sync.aligned.shared::cta.b32 [%0], %1;" \
                 :: "r"(smemaddr), "r"((uint32_t)(n)) : "memory")
#define TC_RELINQ() \
    asm volatile("tcgen05.relinquish_alloc_permit.cta_group::1.sync.aligned;")
#define TC_DEALLOC(tmem, n) \
    asm volatile("tcgen05.dealloc.cta_group::1.sync.aligned.b32 %0, %1;" \
                 :: "r"(tmem), "r"((uint32_t)(n)))
#define TC_WAIT_ST() asm volatile("tcgen05.wait::st.sync.aligned;" ::: "memory")
#define TC_WAIT_LD() asm volatile("tcgen05.wait::ld.sync.aligned;" ::: "memory")
#define TC_FENCE_BEFORE() asm volatile("tcgen05.fence::before_thread_sync;" ::: "memory")
#define TC_FENCE_AFTER()  asm volatile("tcgen05.fence::after_thread_sync;" ::: "memory")
#define TC_COMMIT(mbar) \
    asm volatile("tcgen05.commit.cta_group::1.mbarrier::arrive::one.shared::cluster.b64 [%0];" \
                 :: "r"(mbar) : "memory")
#define MBAR_INIT(mbar, cnt) \
    asm volatile("mbarrier.init.shared.b64 [%0], %1;" :: "r"(mbar), "r"((uint32_t)(cnt)) : "memory")
#define FENCE_PROXY_ASYNC() \
    asm volatile("fence.proxy.async.shared::cta;" ::: "memory")
#define NAMED_BAR(id, n) \
    asm volatile("bar.sync %0, %1;" :: "r"(id), "r"(n) : "memory")
#define NAMED_ARRIVE(id, n) \
    asm volatile("bar.arrive %0, %1;" :: "r"(id), "r"(n) : "memory")

#define MBAR_WAIT(mbar, ph) do {                                             \
    uint32_t _m = (mbar), _p = (uint32_t)(ph), _d;                           \
    asm volatile("{\n\t.reg .pred p;\n\t"                                    \
        "mbarrier.try_wait.parity.acquire.cta.shared::cta.b64 p, [%1], %2;\n\t" \
        "selp.b32 %0, 1, 0, p;\n\t}" : "=r"(_d) : "r"(_m), "r"(_p) : "memory"); \
    if (!_d) {                                                               \
        asm volatile("{\n\t.reg .pred P1;\n\t"                               \
            "WL_%=:\n\t"                                                     \
            "mbarrier.try_wait.parity.acquire.cta.shared::cta.b64 P1, [%0], %1, 0x989680;\n\t" \
            "@P1 bra.uni WD_%=;\n\t"                                         \
            "bra.uni WL_%=;\n\t"                                             \
            "WD_%=:\n\t}" :: "r"(_m), "r"(_p) : "memory");                   \
    }                                                                        \
} while (0)

#define TC_MMA_SS(dtm, adesc, bdesc, en) do {                                \
    uint32_t _e = (en) ? 1u : 0u;                                            \
    asm volatile("{\n\t.reg .pred p;\n\t"                                    \
        "setp.ne.u32 p, %5, 0;\n\t"                                          \
        "tcgen05.mma.cta_group::1.kind::f16 [%0], %1, %2, %3, {%4, %4, %4, %4}, p;\n\t" \
        "}" :: "r"(dtm), "l"(adesc), "l"(bdesc), "r"(IDESC_BF16),            \
               "r"(0u), "r"(_e) : "memory");                                 \
} while (0)

#define TC_MMA_TS(dtm, atm, bdesc, en) do {                                  \
    uint32_t _e = (en) ? 1u : 0u;                                            \
    asm volatile("{\n\t.reg .pred p;\n\t"                                    \
        "setp.ne.u32 p, %5, 0;\n\t"                                          \
        "tcgen05.mma.cta_group::1.kind::f16 [%0], [%1], %2, %3, {%4, %4, %4, %4}, p;\n\t" \
        "}" :: "r"(dtm), "r"(atm), "l"(bdesc), "r"(IDESC_BF16),              \
               "r"(0u), "r"(_e) : "memory");                                 \
} while (0)

#define TC_MMA_TF32_TS(dtm, atm, bdesc, en) do {                             \
    uint32_t _e = (en) ? 1u : 0u;                                            \
    asm volatile("{\n\t.reg .pred p;\n\t"                                    \
        "setp.ne.u32 p, %5, 0;\n\t"                                          \
        "tcgen05.mma.cta_group::1.kind::tf32 [%0], [%1], %2, %3, {%4, %4, %4, %4}, p;\n\t" \
        "}" :: "r"(dtm), "r"(atm), "l"(bdesc), "r"(IDESC_TF32),              \
               "r"(0u), "r"(_e) : "memory");                                 \
} while (0)

#define TC_ST_X16(tmem_addr, r)                                              \
    asm volatile("tcgen05.st.sync.aligned.32x32b.x16.b32 [%0], "             \
        "{%1, %2, %3, %4, %5, %6, %7, %8, "                                  \
        " %9, %10, %11, %12, %13, %14, %15, %16};"                           \
        :: "r"(tmem_addr),                                                   \
           "r"((r)[0]),  "r"((r)[1]),  "r"((r)[2]),  "r"((r)[3]),            \
           "r"((r)[4]),  "r"((r)[5]),  "r"((r)[6]),  "r"((r)[7]),            \
           "r"((r)[8]),  "r"((r)[9]),  "r"((r)[10]), "r"((r)[11]),           \
           "r"((r)[12]), "r"((r)[13]), "r"((r)[14]), "r"((r)[15])            \
        : "memory")

#define TC_ST_X32(tmem_addr, r)                                              \
    asm volatile("tcgen05.st.sync.aligned.32x32b.x32.b32 [%0], "             \
        "{%1, %2, %3, %4, %5, %6, %7, %8, "                                  \
        " %9, %10, %11, %12, %13, %14, %15, %16, "                           \
        " %17, %18, %19, %20, %21, %22, %23, %24, "                          \
        " %25, %26, %27, %28, %29, %30, %31, %32};"                          \
        :: "r"(tmem_addr),                                                   \
           "r"((r)[0]),  "r"((r)[1]),  "r"((r)[2]),  "r"((r)[3]),            \
           "r"((r)[4]),  "r"((r)[5]),  "r"((r)[6]),  "r"((r)[7]),            \
           "r"((r)[8]),  "r"((r)[9]),  "r"((r)[10]), "r"((r)[11]),           \
           "r"((r)[12]), "r"((r)[13]), "r"((r)[14]), "r"((r)[15]),           \
           "r"((r)[16]), "r"((r)[17]), "r"((r)[18]), "r"((r)[19]),           \
           "r"((r)[20]), "r"((r)[21]), "r"((r)[22]), "r"((r)[23]),           \
           "r"((r)[24]), "r"((r)[25]), "r"((r)[26]), "r"((r)[27]),           \
           "r"((r)[28]), "r"((r)[29]), "r"((r)[30]), "r"((r)[31])            \
        : "memory")

#define TC_LD_X32(r, tmem_addr)                                              \
    asm volatile("tcgen05.ld.sync.aligned.32x32b.x32.b32 "                   \
        "{%0, %1, %2, %3, %4, %5, %6, %7, "                                  \
        " %8, %9, %10, %11, %12, %13, %14, %15, "                            \
        " %16, %17, %18, %19, %20, %21, %22, %23, "                          \
        " %24, %25, %26, %27, %28, %29, %30, %31}, [%32];"                   \
        : "=r"((r)[0]),  "=r"((r)[1]),  "=r"((r)[2]),  "=r"((r)[3]),         \
          "=r"((r)[4]),  "=r"((r)[5]),  "=r"((r)[6]),  "=r"((r)[7]),         \
          "=r"((r)[8]),  "=r"((r)[9]),  "=r"((r)[10]), "=r"((r)[11]),        \
          "=r"((r)[12]), "=r"((r)[13]), "=r"((r)[14]), "=r"((r)[15]),        \
          "=r"((r)[16]), "=r"((r)[17]), "=r"((r)[18]), "=r"((r)[19]),        \
          "=r"((r)[20]), "=r"((r)[21]), "=r"((r)[22]), "=r"((r)[23]),        \
          "=r"((r)[24]), "=r"((r)[25]), "=r"((r)[26]), "=r"((r)[27]),        \
          "=r"((r)[28]), "=r"((r)[29]), "=r"((r)[30]), "=r"((r)[31])         \
        : "r"(tmem_addr))

static constexpr unsigned long long SMEM_DESC_BASE =
    (2ull << 61) | (1ull << 46) | (64ull << 32) | (1ull << 16);
__device__ __forceinline__ uint64_t mk_desc(uint32_t addr) {
    return SMEM_DESC_BASE | ((uint64_t)(addr >> 4) & 0x3FFF);
}
// bf16: K-step = 16 elems = 32B; tf32: K-step = 8 elems = 32B. Same koff.
__device__ __forceinline__ uint64_t koff(int s) {
    return (uint64_t)((s >> 2) * 1024 + (s & 3) * 2);
}

#endif // sm_103a device helpers

// ---------------- small kernels ------------------------------------------
__global__ void k_detect(const int* ei32) {
    if (blockIdx.x == 0 && threadIdx.x == 0) {
        int is64 = 1;
        #pragma unroll 1
        for (int i = 0; i < 64; ++i)
            if (ei32[2 * i + 1] != 0) { is64 = 0; break; }
        g_is64 = is64;
    }
}
__global__ void k_convert_zero(const void* ei) {
    size_t i = (size_t)blockIdx.x * blockDim.x + threadIdx.x;
    if (i < N_EDGES) {
        if (g_is64) {
            const long long* p = (const long long*)ei;
            g_row[i] = (int)p[i];
            g_col[i] = (int)p[(size_t)N_EDGES + i];
        } else {
            const int* p = (const int*)ei;
            g_row[i] = p[i];
            g_col[i] = p[N_EDGES + i];
        }
    }
    if (i < (size_t)N_NODES * D) g_agg[i] = 0.0f;
}
// weight prep: all four weight matrices
__global__ void k_prep(const float* __restrict__ W1, const float* __restrict__ W2,
                       const float* __restrict__ NW1, const float* __restrict__ NW2) {
    int i = blockIdx.x * blockDim.x + threadIdx.x;
    if (i < 128 * K1PAD) {                          // edge W1 bf16
        int n = i / K1PAD, k = i % K1PAD;
        float v = (k < K1) ? W1[(size_t)k * 128 + n] : 0.0f;
        g_W1B[swz(abyte(n, k)) >> 1] = bf16_bits(v);
        return;
    }
    i -= 128 * K1PAD;
    if (i < 128 * 128) {                            // edge W2 bf16
        int n = i / 128, k = i % 128;
        g_W2B[swz(abyte(n, k)) >> 1] = bf16_bits(W2[(size_t)k * 128 + n]);
        return;
    }
    i -= 128 * 128;
    if (i < 128 * 256) {                            // node W1 tf32 (K=256)
        int n = i / 256, k = i % 256;
        g_NW1B[swz(abyte32(n, k)) >> 2] = f2tf32(NW1[(size_t)k * 128 + n]);
        return;
    }
    i -= 128 * 256;
    if (i < 128 * 128) {                            // node W2 tf32 (K=128)
        int n = i / 128, k = i % 128;
        g_NW2B[swz(abyte32(n, k)) >> 2] = f2tf32(NW2[(size_t)k * 128 + n]);
    }
}

// ---------------- fused edge kernel (pipelined MMA1) ----------------------
__global__ __launch_bounds__(256, 1) void k_edge_fused(
    const float* __restrict__ x, const float* __restrict__ ea,
    const float* __restrict__ eb1, const float* __restrict__ eb2,
    const float* __restrict__ eW1raw, const float* __restrict__ eW2raw,
    int nblocks)
{
#if defined(__CUDA_ARCH__) && defined(__CUDA_ARCH_FEAT_SM103_ALL)
    extern __shared__ uint32_t dsm[];
    __shared__ float s_eb1[D], s_eb2[D];
    __shared__ uint32_t s_tmem[1];
    __shared__ __align__(8) unsigned long long s_mbar1, s_mbar2;

    const int tid = threadIdx.x;
    const int wid = tid >> 5;
    const int lane = tid & 31;

    const uint32_t dyn_base = smem_u32(dsm);
    const uint32_t ws1 = (dyn_base + 1023u) & ~1023u;
    const uint32_t ws2 = ws1 + W1B_BYTES;
    const uint32_t wsA = ws2 + W2B_BYTES;
    uint32_t* w1p = dsm + ((ws1 - dyn_base) >> 2);

    {
        uint4* dst = (uint4*)w1p; const uint4* src = (const uint4*)g_W1B;
        for (int i = tid; i < (W1B_BYTES + W2B_BYTES) / 16; i += 256) dst[i] = src[i];
        if (tid < D) { s_eb1[tid] = eb1[tid]; s_eb2[tid] = eb2[tid]; }
        for (int i = tid; i < 128 * 12; i += 256) {
            int row = i / 12, j = i % 12;
            sts8(wsA + swz(abyte(row, 272 + j * 4)), 0u, 0u);
        }
    }
    if (wid == 0) TC_ALLOC(smem_u32(s_tmem), 512);
    if (tid == 0) { MBAR_INIT(smem_u32(&s_mbar1), 1); MBAR_INIT(smem_u32(&s_mbar2), 1); }
    __syncthreads();
    const uint32_t tbase = s_tmem[0];
    const uint32_t mbar1 = smem_u32(&s_mbar1);
    const uint32_t mbar2 = smem_u32(&s_mbar2);
    const uint64_t a1d = mk_desc(wsA);
    const uint64_t w1d = mk_desc(ws1);
    const uint64_t w2d = mk_desc(ws2);

    auto gather = [&](int tile) {
        const int gw = wid;
        const int e0 = tile * TM + gw * 32;
        const int myr = g_row[e0 + lane];
        const int myc = g_col[e0 + lane];
        #pragma unroll 8
        for (int i = 0; i < 32; ++i) {
            const int el = gw * 32 + i;
            const int r = __shfl_sync(0xffffffffu, myr, i);
            const int c = __shfl_sync(0xffffffffu, myc, i);
            float4 v = *(const float4*)(x + (size_t)r * D + lane * 4);
            sts8(wsA + swz(abyte(el, lane * 4)),
                 pack_bf16x2(v.x, v.y), pack_bf16x2(v.z, v.w));
            v = *(const float4*)(x + (size_t)c * D + lane * 4);
            sts8(wsA + swz(abyte(el, 128 + lane * 4)),
                 pack_bf16x2(v.x, v.y), pack_bf16x2(v.z, v.w));
        }
        #pragma unroll
        for (int i = 0; i < 4; ++i) {
            const int el = gw * 32 + i * 8 + (lane >> 2);
            const int e = tile * TM + el;
            float4 v = *(const float4*)(ea + (size_t)e * DE + (lane & 3) * 4);
            sts8(wsA + swz(abyte(el, 256 + (lane & 3) * 4)),
                 pack_bf16x2(v.x, v.y), pack_bf16x2(v.z, v.w));
        }
    };

    auto e2_half = [&](int tile, int c0) {
        const int e = tile * TM + (wid & 3) * 32 + lane;
        float* aggp = g_agg + (size_t)g_row[e] * D;
        uint32_t d0[32], d1[32];
        TC_LD_X32(d0, tbase + TMEM_D2 + c0 * 32);
        TC_LD_X32(d1, tbase + TMEM_D2 + (c0 + 1) * 32);
        TC_WAIT_LD();
        #pragma unroll
        for (int q = 0; q < 8; ++q) {
            float v0 = silu_f(__uint_as_float(d0[q*4+0]) + s_eb2[c0*32+q*4+0]);
            float v1 = silu_f(__uint_as_float(d0[q*4+1]) + s_eb2[c0*32+q*4+1]);
            float v2 = silu_f(__uint_as_float(d0[q*4+2]) + s_eb2[c0*32+q*4+2]);
            float v3 = silu_f(__uint_as_float(d0[q*4+3]) + s_eb2[c0*32+q*4+3]);
            asm volatile("red.global.add.v4.f32 [%0], {%1,%2,%3,%4};"
                         :: "l"(aggp + c0 * 32 + q * 4),
                            "f"(v0), "f"(v1), "f"(v2), "f"(v3) : "memory");
        }
        #pragma unroll
        for (int q = 0; q < 8; ++q) {
            float v0 = silu_f(__uint_as_float(d1[q*4+0]) + s_eb2[(c0+1)*32+q*4+0]);
            float v1 = silu_f(__uint_as_float(d1[q*4+1]) + s_eb2[(c0+1)*32+q*4+1]);
            float v2 = silu_f(__uint_as_float(d1[q*4+2]) + s_eb2[(c0+1)*32+q*4+2]);
            float v3 = silu_f(__uint_as_float(d1[q*4+3]) + s_eb2[(c0+1)*32+q*4+3]);
            asm volatile("red.global.add.v4.f32 [%0], {%1,%2,%3,%4};"
                         :: "l"(aggp + (c0 + 1) * 32 + q * 4),
                            "f"(v0), "f"(v1), "f"(v2), "f"(v3) : "memory");
        }
    };

    // prologue: gather tile0, then issue MMA1(tile0)
    if (wid < 4 && blockIdx.x < NTILES) { gather(blockIdx.x); FENCE_PROXY_ASYNC(); }
    __syncthreads();
    if (wid == 4 && blockIdx.x < NTILES) {
        TC_FENCE_AFTER();
        if (elect_one()) {
            #pragma unroll 1
            for (int s = 0; s < 17; ++s)
                TC_MMA_SS(tbase + TMEM_D1, a1d + koff(s), w1d + koff(s), s > 0);
            TC_COMMIT(mbar1);
        }
    }

    int ph1 = 0, ph2 = 0;
    for (int tile = blockIdx.x; tile < NTILES; tile += nblocks) {
        const bool has_next = (tile + nblocks < NTILES);

        if (wid < 4) {
            // A1 consumed once MMA1(tile) completes
            MBAR_WAIT(mbar1, ph1);
            if (has_next) {
                gather(tile + nblocks); FENCE_PROXY_ASYNC();
                NAMED_ARRIVE(2, 160);
            }
            MBAR_WAIT(mbar2, ph2);
            TC_FENCE_AFTER();
            e2_half(tile, 2);
            TC_FENCE_BEFORE();
        } else {
            MBAR_WAIT(mbar1, ph1);
            TC_FENCE_AFTER();

            // E1: D1 -> bias+silu -> A2
            #pragma unroll 1
            for (int half = 0; half < 2; ++half) {
                uint32_t d0[32], d1[32], a0[16], a1r[16];
                const int c0 = half * 2;
                TC_LD_X32(d0, tbase + TMEM_D1 + c0 * 32);
                TC_LD_X32(d1, tbase + TMEM_D1 + (c0 + 1) * 32);
                TC_WAIT_LD();
                #pragma unroll
                for (int m = 0; m < 16; ++m) {
                    float v0 = silu_f(__uint_as_float(d0[2*m])   + s_eb1[c0*32 + 2*m]);
                    float v1 = silu_f(__uint_as_float(d0[2*m+1]) + s_eb1[c0*32 + 2*m+1]);
                    a0[m] = pack_bf16x2(v0, v1);
                }
                #pragma unroll
                for (int m = 0; m < 16; ++m) {
                    float v0 = silu_f(__uint_as_float(d1[2*m])   + s_eb1[(c0+1)*32 + 2*m]);
                    float v1 = silu_f(__uint_as_float(d1[2*m+1]) + s_eb1[(c0+1)*32 + 2*m+1]);
                    a1r[m] = pack_bf16x2(v0, v1);
                }
                const uint32_t wo = (uint32_t)(wid & 3) << 21;
                TC_ST_X16(tbase + TMEM_A2 + c0 * 16 + wo, a0);
                TC_ST_X16(tbase + TMEM_A2 + (c0 + 1) * 16 + wo, a1r);
            }
            TC_WAIT_ST();
            TC_FENCE_BEFORE();
            NAMED_BAR(1, 128);     // E1 done: A2 ready, D1 free

            if (wid == 4) {
                TC_FENCE_AFTER();
                if (elect_one()) {
                    #pragma unroll 1
                    for (int s = 0; s < 8; ++s)
                        TC_MMA_TS(tbase + TMEM_D2, tbase + TMEM_A2 + s * 8,
                                  w2d + koff(s), s > 0);
                    TC_COMMIT(mbar2);
                }
                if (has_next) {
                    NAMED_BAR(2, 160);   // gather(t+1) complete
                    if (elect_one()) {
                        #pragma unroll 1
                        for (int s = 0; s < 17; ++s)
                            TC_MMA_SS(tbase + TMEM_D1, a1d + koff(s), w1d + koff(s), s > 0);
                        TC_COMMIT(mbar1);
                    }
                }
            }
            MBAR_WAIT(mbar2, ph2);
            TC_FENCE_AFTER();
            e2_half(tile, 0);
            TC_FENCE_BEFORE();
        }
        ph1 ^= 1; ph2 ^= 1;
    }

    __syncthreads();
    if (wid == 0) { TC_RELINQ(); TC_DEALLOC(tbase, 512); }

#else
    // plain-sm_103 fallback (never selected on GB300)
    const int tid = threadIdx.x;
    if (tid >= TM) return;
    for (int tile = blockIdx.x; tile < NTILES; tile += nblocks) {
        const int e = tile * TM + tid;
        const int r = g_row[e], c = g_col[e];
        float a[K1];
        #pragma unroll 4
        for (int j = 0; j < D; ++j) { a[j] = x[(size_t)r * D + j]; a[D + j] = x[(size_t)c * D + j]; }
        #pragma unroll
        for (int j = 0; j < DE; ++j) a[2 * D + j] = ea[(size_t)e * DE + j];
        float h[D];
        for (int n = 0; n < D; ++n) {
            float s = eb1[n];
            for (int k = 0; k < K1; ++k) s = fmaf(a[k], eW1raw[(size_t)k * D + n], s);
            h[n] = silu_f(s);
        }
        for (int n = 0; n < D; ++n) {
            float s = eb2[n];
            for (int k = 0; k < D; ++k) s = fmaf(h[k], eW2raw[(size_t)k * D + n], s);
            atomicAdd(g_agg + (size_t)r * D + n, silu_f(s));
        }
    }
#endif
}

// ---------------- fused node kernel (tcgen05 tf32, TS mode) ---------------
__global__ __launch_bounds__(128, 1) void k_node_fused(
    const float* __restrict__ x,
    const float* __restrict__ nb1, const float* __restrict__ nb2,
    const float* __restrict__ nW1raw, const float* __restrict__ nW2raw,
    float* __restrict__ out, int nblocks)
{
#if defined(__CUDA_ARCH__) && defined(__CUDA_ARCH_FEAT_SM103_ALL)
    extern __shared__ uint32_t dsm[];
    __shared__ float s_b1[D], s_b2[D];
    __shared__ uint32_t s_tmem[1];
    __shared__ __align__(8) unsigned long long s_mbar;

    const int tid = threadIdx.x;
    const int wid = tid >> 5;
    const int lane = tid & 31;
    const uint32_t woff = (uint32_t)wid << 21;

    const uint32_t dyn_base = smem_u32(dsm);
    const uint32_t ws1 = (dyn_base + 1023u) & ~1023u;       // nW1 tf32 128KB
    const uint32_t ws2 = ws1 + NW1_WORDS * 4;               // nW2 tf32 64KB
    uint32_t* w1p = dsm + ((ws1 - dyn_base) >> 2);

    {
        uint4* dst = (uint4*)w1p; const uint4* src = (const uint4*)g_NW1B;
        for (int i = tid; i < (NW1_WORDS + NW2_WORDS) / 4; i += 128) dst[i] = src[i];
        if (tid < D) { s_b1[tid] = nb1[tid]; s_b2[tid] = nb2[tid]; }
    }
    if (wid == 0) TC_ALLOC(smem_u32(s_tmem), 512);
    if (tid == 0) MBAR_INIT(smem_u32(&s_mbar), 1);
    __syncthreads();
    const uint32_t tbase = s_tmem[0];
    const uint32_t mbar = smem_u32(&s_mbar);
    const uint64_t w1d = mk_desc(ws1);
    const uint64_t w2d = mk_desc(ws2);

    int ph = 0;
    for (int tile = blockIdx.x; tile < NNT; tile += nblocks) {
        __syncthreads();   // prev tile's A2/D2 reads done before A1 overwrite

        // ---- load [x|agg] row tid -> TMEM A1 (tf32, cols 0..255) ----
        {
            int n = tile * 128 + tid;
            if (n >= N_NODES) n = N_NODES - 1;
            const float4* xr = (const float4*)(x + (size_t)n * D);
            const float4* ar = (const float4*)(g_agg + (size_t)n * D);
            uint32_t a[32];
            #pragma unroll 1
            for (int ch = 0; ch < 4; ++ch) {
                #pragma unroll
                for (int q = 0; q < 8; ++q) {
                    float4 v = xr[ch * 8 + q];
                    a[q*4+0] = f2tf32(v.x); a[q*4+1] = f2tf32(v.y);
                    a[q*4+2] = f2tf32(v.z); a[q*4+3] = f2tf32(v.w);
                }
                TC_ST_X32(tbase + ch * 32 + woff, a);
            }
            #pragma unroll 1
            for (int ch = 0; ch < 4; ++ch) {
                #pragma unroll
                for (int q = 0; q < 8; ++q) {
                    float4 v = ar[ch * 8 + q];
                    a[q*4+0] = f2tf32(v.x); a[q*4+1] = f2tf32(v.y);
                    a[q*4+2] = f2tf32(v.z); a[q*4+3] = f2tf32(v.w);
                }
                TC_ST_X32(tbase + 128 + ch * 32 + woff, a);
            }
        }
        TC_WAIT_ST();
        TC_FENCE_BEFORE();
        __syncthreads();

        // ---- MMA1 (tf32 TS): D1 = A1 @ nW1, K=256 -> 32 steps ----
        if (wid == 0) {
            TC_FENCE_AFTER();
            if (elect_one()) {
                #pragma unroll 1
                for (int s = 0; s < 32; ++s)
                    TC_MMA_TF32_TS(tbase + 256, tbase + s * 8, w1d + koff(s), s > 0);
                TC_COMMIT(mbar);
            }
        }
        MBAR_WAIT(mbar, ph); ph ^= 1;
        TC_FENCE_AFTER();

        // ---- E1: D1 -> bias+silu -> A2 (tf32, cols 0..127) ----
        #pragma unroll 1
        for (int ch = 0; ch < 4; ++ch) {
            uint32_t dreg[32], areg[32];
            TC_LD_X32(dreg, tbase + 256 + ch * 32);
            TC_WAIT_LD();
            #pragma unroll
            for (int j = 0; j < 32; ++j)
                areg[j] = f2tf32(silu_f(__uint_as_float(dreg[j]) + s_b1[ch * 32 + j]));
            TC_ST_X32(tbase + ch * 32 + woff, areg);
        }
        TC_WAIT_ST();
        TC_FENCE_BEFORE();
        __syncthreads();

        // ---- MMA2 (tf32 TS): D2 = A2 @ nW2, K=128 -> 16 steps ----
        if (wid == 0) {
            TC_FENCE_AFTER();
            if (elect_one()) {
                #pragma unroll 1
                for (int s = 0; s < 16; ++s)
                    TC_MMA_TF32_TS(tbase + 128, tbase + s * 8, w2d + koff(s), s > 0);
                TC_COMMIT(mbar);
            }
        }
        MBAR_WAIT(mbar, ph); ph ^= 1;
        TC_FENCE_AFTER();

        // ---- E2: out = x + D2 + nb2 ----
        {
            const int n = tile * 128 + wid * 32 + lane;
            const bool valid = (n < N_NODES);
            const float4* xr = (const float4*)(x + (size_t)n * D);
            float4* orow = (float4*)(out + (size_t)n * D);
            #pragma unroll 1
            for (int ch = 0; ch < 4; ++ch) {
                uint32_t dreg[32];
                TC_LD_X32(dreg, tbase + 128 + ch * 32);
                TC_WAIT_LD();
                if (valid) {
                    #pragma unroll
                    for (int q = 0; q < 8; ++q) {
                        float4 xv = xr[ch * 8 + q];
                        float4 o;
                        o.x = xv.x + __uint_as_float(dreg[q*4+0]) + s_b2[ch*32+q*4+0];
                        o.y = xv.y + __uint_as_float(dreg[q*4+1]) + s_b2[ch*32+q*4+1];
                        o.z = xv.z + __uint_as_float(dreg[q*4+2]) + s_b2[ch*32+q*4+2];
                        o.w = xv.w + __uint_as_float(dreg[q*4+3]) + s_b2[ch*32+q*4+3];
                        orow[ch * 8 + q] = o;
                    }
                }
            }
            TC_FENCE_BEFORE();
        }
    }

    __syncthreads();
    if (wid == 0) { TC_RELINQ(); TC_DEALLOC(tbase, 512); }

#else
    // plain-sm_103 fallback (never selected on GB300)
    const int tid = threadIdx.x;
    for (int n = blockIdx.x * 128 + tid; n < N_NODES; n += nblocks * 128) {
        float t[D];
        for (int o = 0; o < D; ++o) {
            float s = nb1[o];
            for (int k = 0; k < D; ++k) {
                s = fmaf(x[(size_t)n * D + k], nW1raw[(size_t)k * D + o], s);
                s = fmaf(g_agg[(size_t)n * D + k], nW1raw[(size_t)(D + k) * D + o], s);
            }
            t[o] = silu_f(s);
        }
        for (int o = 0; o < D; ++o) {
            float s = nb2[o];
            for (int k = 0; k < D; ++k) s = fmaf(t[k], nW2raw[(size_t)k * D + o], s);
            out[(size_t)n * D + o] = x[(size_t)n * D + o] + s;
        }
    }
#endif
}

// ---------------- launch --------------------------------------------------
extern "C" void kernel_launch(void* const* d_in, const int* in_sizes, int n_in,
                              void* d_out, int out_size)
{
    const float* x   = (const float*)d_in[0];
    const void*  ei  = d_in[1];
    const float* ea  = (const float*)d_in[2];
    const float* eW1 = (const float*)d_in[3];
    const float* eb1 = (const float*)d_in[4];
    const float* eW2 = (const float*)d_in[5];
    const float* eb2 = (const float*)d_in[6];
    const float* nW1 = (const float*)d_in[7];
    const float* nb1 = (const float*)d_in[8];
    const float* nW2 = (const float*)d_in[9];
    const float* nb2 = (const float*)d_in[10];
    float* out = (float*)d_out;

    int sms = 148;
    cudaDeviceGetAttribute(&sms, cudaDevAttrMultiProcessorCount, 0);

    const int s_edge = 1024 + W1B_BYTES + W2B_BYTES + A1B_BYTES;     // 197,632
    const int s_node = 1024 + (NW1_WORDS + NW2_WORDS) * 4;           // 197,632

    cudaFuncSetAttribute(k_edge_fused, cudaFuncAttributeMaxDynamicSharedMemorySize, s_edge);
    cudaFuncSetAttribute(k_node_fused, cudaFuncAttributeMaxDynamicSharedMemorySize, s_node);

    const int prep_elems = 128 * K1PAD + 128 * 128 + 128 * 256 + 128 * 128;
    const size_t cz = (size_t)N_NODES * D;

    k_detect<<<1, 1>>>((const int*)ei);
    k_convert_zero<<<(int)((cz + 255) / 256), 256>>>(ei);
    k_prep<<<(prep_elems + 255) / 256, 256>>>(eW1, eW2, nW1, nW2);
    k_edge_fused<<<sms, 256, s_edge>>>(x, ea, eb1, eb2, eW1, eW2, sms);
    k_node_fused<<<sms, 128, s_node>>>(x, nb1, nb2, nW1, nW2, out, sms);
}